// round 1
// baseline (speedup 1.0000x reference)
#include <cuda_runtime.h>
#include <cuda_bf16.h>
#include <cstdint>

#define TT 1024
#define DD 1024
#define HDIM 64
#define NHEADS 32
#define ATT_SCALE 0.125f   // 64^-0.5
#define HEAD_SZ (1024*1024)

// ---------------- scratch (device globals; allocation-free) ----------------
__device__ float g_q[TT*DD];
__device__ float g_k[TT*DD];
__device__ float g_v[TT*DD];
__device__ float g_wlow[TT*32];
__device__ float g_wraw[TT*4096];
__device__ float g_btmp[TT*32];
__device__ float g_betah[NHEADS*TT];
__device__ float g_wdir[NHEADS*TT*HDIM];
__device__ float g_Mw[NHEADS*HEAD_SZ];   // 128 MB
__device__ float g_BR[NHEADS*HEAD_SZ];   // rhs -> Bmat in place
__device__ float g_QK[NHEADS*HEAD_SZ];   // qk -> logits -> p in place
__device__ float g_QW[NHEADS*HEAD_SZ];
__device__ float g_Tinv[NHEADS*16*64*64];
__device__ float g_O2[TT*2048];

// ---------------- tile helpers ----------------
// Load a 64x64 tile whose source is contiguous along k; store transposed S[k][m].
__device__ __forceinline__ void load_tile_T(float (*S)[64], const float* src, int ld, int tid) {
    int r  = tid >> 2;
    int kq = (tid & 3) * 4;
#pragma unroll
    for (int q = 0; q < 4; q++) {
        int kk = kq + q * 16;
        float4 t4 = *(const float4*)(src + (size_t)r * ld + kk);
        S[kk+0][r] = t4.x; S[kk+1][r] = t4.y; S[kk+2][r] = t4.z; S[kk+3][r] = t4.w;
    }
}
// Load a 64x64 tile contiguous along n; store direct S[k][n].
__device__ __forceinline__ void load_tile_D(float (*S)[64], const float* src, int ld, int tid) {
    int kb = tid >> 4;
    int n4 = (tid & 15) * 4;
#pragma unroll
    for (int q = 0; q < 4; q++) {
        int k = kb + q * 16;
        *(float4*)&S[k][n4] = *(const float4*)(src + (size_t)k * ld + n4);
    }
}

template<bool SUB>
__device__ __forceinline__ void mm64(const float (*As)[64], const float (*Bs)[64],
                                     float acc[4][4], int tr4, int tc4) {
#pragma unroll
    for (int kk = 0; kk < 64; kk++) {
        float4 a4 = *(const float4*)&As[kk][tr4];
        float4 b4 = *(const float4*)&Bs[kk][tc4];
        float a[4] = {a4.x, a4.y, a4.z, a4.w};
        float b[4] = {b4.x, b4.y, b4.z, b4.w};
#pragma unroll
        for (int i = 0; i < 4; i++)
#pragma unroll
            for (int j = 0; j < 4; j++) {
                if (SUB) acc[i][j] -= a[i] * b[j];
                else     acc[i][j] += a[i] * b[j];
            }
    }
}

// ---------------- generic C = A @ B^T (row-major), tile 64x64, BK=16 ----------------
__global__ __launch_bounds__(256)
void gemm_abt(const float* __restrict__ A, const float* __restrict__ B,
              float* __restrict__ C, int M, int N, int K,
              int lda, int ldb, int ldc) {
    __shared__ float As[16][64], Bs[16][64];
    int n0 = blockIdx.x * 64, m0 = blockIdx.y * 64;
    int tid = threadIdx.x;
    int r  = tid >> 2;
    int kq = (tid & 3) * 4;
    int tr4 = (tid >> 4) * 4, tc4 = (tid & 15) * 4;
    float acc[4][4] = {};
    for (int k0 = 0; k0 < K; k0 += 16) {
        float4 a4 = *(const float4*)(A + (size_t)(m0 + r) * lda + k0 + kq);
        As[kq+0][r]=a4.x; As[kq+1][r]=a4.y; As[kq+2][r]=a4.z; As[kq+3][r]=a4.w;
        if (n0 + r < N) {
            float4 b4 = *(const float4*)(B + (size_t)(n0 + r) * ldb + k0 + kq);
            Bs[kq+0][r]=b4.x; Bs[kq+1][r]=b4.y; Bs[kq+2][r]=b4.z; Bs[kq+3][r]=b4.w;
        } else {
            Bs[kq+0][r]=0.f; Bs[kq+1][r]=0.f; Bs[kq+2][r]=0.f; Bs[kq+3][r]=0.f;
        }
        __syncthreads();
#pragma unroll
        for (int kk = 0; kk < 16; kk++) {
            float4 a = *(const float4*)&As[kk][tr4];
            float4 b = *(const float4*)&Bs[kk][tc4];
            float av[4]={a.x,a.y,a.z,a.w}, bv[4]={b.x,b.y,b.z,b.w};
#pragma unroll
            for (int i=0;i<4;i++)
#pragma unroll
                for (int j=0;j<4;j++) acc[i][j] += av[i]*bv[j];
        }
        __syncthreads();
    }
#pragma unroll
    for (int i = 0; i < 4; i++)
#pragma unroll
        for (int j = 0; j < 4; j++) {
            int col = n0 + tc4 + j;
            if (col < N) C[(size_t)(m0 + tr4 + i) * ldc + col] = acc[i][j];
        }
}

// ---------------- per-head A @ B^T with causal masking ----------------
// mode 1: strict lower (col<row), mode 2: inclusive lower (col<=row). rowscale optional.
__global__ __launch_bounds__(256)
void head_gemm(const float* __restrict__ Abase, int a_shift, int a_per, int a_ld,
               const float* __restrict__ Bbase, int b_shift, int b_per, int b_ld,
               const float* __restrict__ rowscale, float* __restrict__ C, int mode) {
    int jt = blockIdx.x, it = blockIdx.y, h = blockIdx.z;
    if (jt > it) return;
    __shared__ float As[64][64], Bs[64][64];
    int tid = threadIdx.x;
    int tr4 = (tid >> 4) * 4, tc4 = (tid & 15) * 4;
    const float* A = Abase + (size_t)(a_shift ? (h >> 1) : h) * a_per + (size_t)(it*64) * a_ld;
    const float* B = Bbase + (size_t)(b_shift ? (h >> 1) : h) * b_per + (size_t)(jt*64) * b_ld;
    load_tile_T(As, A, a_ld, tid);
    load_tile_T(Bs, B, b_ld, tid);
    __syncthreads();
    float acc[4][4] = {};
    mm64<false>(As, Bs, acc, tr4, tc4);
    float* Ch = C + (size_t)h * HEAD_SZ;
#pragma unroll
    for (int i = 0; i < 4; i++) {
        int row = it*64 + tr4 + i;
        float sc = rowscale ? rowscale[h*TT + row] : 1.f;
        float o[4];
#pragma unroll
        for (int j = 0; j < 4; j++) {
            int col = jt*64 + tc4 + j;
            float v = acc[i][j] * sc;
            if (mode == 1 && col >= row) v = 0.f;
            if (mode == 2 && col >  row) v = 0.f;
            o[j] = v;
        }
        *(float4*)&Ch[(size_t)row*TT + jt*64 + tc4] = make_float4(o[0],o[1],o[2],o[3]);
    }
}

// ---------------- invert (I + L) for every 64x64 diagonal block ----------------
__global__ __launch_bounds__(64)
void compute_tinv(const float* __restrict__ Mw, float* __restrict__ Tinv) {
    __shared__ float L[64][65];
    __shared__ float X[64][65];
    int ch = blockIdx.x, h = blockIdx.y, c = threadIdx.x;
    const float* M = Mw + (size_t)h * HEAD_SZ + (size_t)(ch*64) * TT + ch*64;
    for (int r = 0; r < 64; r++) {
        L[r][c] = M[(size_t)r*TT + c];
        X[r][c] = (r == c) ? 1.f : 0.f;
    }
    __syncthreads();
    for (int r = 1; r < 64; r++) {
        if (c < r) {
            float acc = 0.f;
            for (int s = c; s < r; s++) acc += L[r][s] * X[s][c];
            X[r][c] = -acc;
        }
        __syncthreads();
    }
    float* out = Tinv + ((size_t)(h*16 + ch)) * 4096;
    for (int r = 0; r < 64; r++) out[r*64 + c] = X[r][c];
}

// ---------------- blocked forward substitution, chunk ci ----------------
// B[ci, jt] = Tinv_ci @ ( rhs[ci, jt] - sum_{s=jt..ci-1} Mw[ci, s] @ B[s, jt] )
__global__ __launch_bounds__(256)
void solve_chunk(int ci, const float* __restrict__ Mw,
                 float* __restrict__ BR, const float* __restrict__ Tinv) {
    int jt = blockIdx.x, h = blockIdx.y;
    __shared__ float As[64][64], Bs[64][64];
    int tid = threadIdx.x;
    int tr4 = (tid >> 4) * 4, tc4 = (tid & 15) * 4;
    const float* MwH = Mw + (size_t)h * HEAD_SZ;
    float* BRH = BR + (size_t)h * HEAD_SZ;
    float acc[4][4];
#pragma unroll
    for (int i = 0; i < 4; i++) {
        float4 v = *(const float4*)&BRH[(size_t)(ci*64 + tr4 + i)*TT + jt*64 + tc4];
        acc[i][0]=v.x; acc[i][1]=v.y; acc[i][2]=v.z; acc[i][3]=v.w;
    }
    for (int s = jt; s < ci; s++) {
        load_tile_T(As, MwH + (size_t)(ci*64)*TT + s*64, TT, tid);
        load_tile_D(Bs, BRH + (size_t)(s*64)*TT + jt*64, TT, tid);
        __syncthreads();
        mm64<true>(As, Bs, acc, tr4, tc4);
        __syncthreads();
    }
    // stage P into As, Tinv^T into Bs
#pragma unroll
    for (int i = 0; i < 4; i++)
        *(float4*)&As[tr4 + i][tc4] = make_float4(acc[i][0], acc[i][1], acc[i][2], acc[i][3]);
    load_tile_T(Bs, Tinv + ((size_t)(h*16 + ci)) * 4096, 64, tid);
    __syncthreads();
#pragma unroll
    for (int i=0;i<4;i++)
#pragma unroll
        for (int j=0;j<4;j++) acc[i][j] = 0.f;
    mm64<false>(Bs, As, acc, tr4, tc4);   // Bs[s][r]=Tinv[r][s], As[s][c]=P[s][c]
#pragma unroll
    for (int i = 0; i < 4; i++)
        *(float4*)&BRH[(size_t)(ci*64 + tr4 + i)*TT + jt*64 + tc4] =
            make_float4(acc[i][0], acc[i][1], acc[i][2], acc[i][3]);
}

// ---------------- logits = (qk - QW @ Bmat) * scale, causal tiles only ----------------
__global__ __launch_bounds__(256)
void logits_gemm(const float* __restrict__ QW, const float* __restrict__ BR,
                 float* __restrict__ QK) {
    int jt = blockIdx.x, it = blockIdx.y, h = blockIdx.z;
    if (jt > it) return;
    __shared__ float As[64][64], Bs[64][64];
    int tid = threadIdx.x;
    int tr4 = (tid >> 4) * 4, tc4 = (tid & 15) * 4;
    const float* QWh = QW + (size_t)h * HEAD_SZ;
    const float* BRh = BR + (size_t)h * HEAD_SZ;
    float* QKh = QK + (size_t)h * HEAD_SZ;
    float acc[4][4] = {};
    for (int kt = jt; kt <= it; kt++) {
        load_tile_T(As, QWh + (size_t)(it*64)*TT + kt*64, TT, tid);
        load_tile_D(Bs, BRh + (size_t)(kt*64)*TT + jt*64, TT, tid);
        __syncthreads();
        mm64<false>(As, Bs, acc, tr4, tc4);
        __syncthreads();
    }
#pragma unroll
    for (int i = 0; i < 4; i++) {
        size_t off = (size_t)(it*64 + tr4 + i)*TT + jt*64 + tc4;
        float4 q = *(const float4*)&QKh[off];
        *(float4*)&QKh[off] = make_float4((q.x - acc[i][0]) * ATT_SCALE,
                                          (q.y - acc[i][1]) * ATT_SCALE,
                                          (q.z - acc[i][2]) * ATT_SCALE,
                                          (q.w - acc[i][3]) * ATT_SCALE);
    }
}

// ---------------- causal row softmax, in place ----------------
__global__ __launch_bounds__(128)
void softmax_rows(float* __restrict__ P) {
    int i = blockIdx.x, h = blockIdx.y, tid = threadIdx.x;
    float* row = P + (size_t)h * HEAD_SZ + (size_t)i * TT;
    int n = i + 1;
    __shared__ float sh[4];
    float mx = -1e30f;
    for (int j = tid; j < n; j += 128) mx = fmaxf(mx, row[j]);
#pragma unroll
    for (int o = 16; o; o >>= 1) mx = fmaxf(mx, __shfl_xor_sync(~0u, mx, o));
    if ((tid & 31) == 0) sh[tid >> 5] = mx;
    __syncthreads();
    mx = fmaxf(fmaxf(sh[0], sh[1]), fmaxf(sh[2], sh[3]));
    __syncthreads();
    float sum = 0.f;
    for (int j = tid; j < n; j += 128) { float e = __expf(row[j] - mx); row[j] = e; sum += e; }
#pragma unroll
    for (int o = 16; o; o >>= 1) sum += __shfl_xor_sync(~0u, sum, o);
    if ((tid & 31) == 0) sh[tid >> 5] = sum;
    __syncthreads();
    sum = sh[0] + sh[1] + sh[2] + sh[3];
    float inv = 1.f / sum;
    for (int j = tid; j < n; j += 128) row[j] *= inv;
}

// ---------------- O2[i, h*64+d] = sum_{j<=i} P[i,j] * V[j, (h>>1)*64+d] ----------------
__global__ __launch_bounds__(256)
void pv_gemm(const float* __restrict__ P, const float* __restrict__ V,
             float* __restrict__ O2) {
    int it = blockIdx.x, h = blockIdx.y;
    __shared__ float As[64][64], Bs[64][64];
    int tid = threadIdx.x;
    int tr4 = (tid >> 4) * 4, tc4 = (tid & 15) * 4;
    const float* Ph = P + (size_t)h * HEAD_SZ;
    const float* Vh = V + (size_t)(h >> 1) * 64;
    float acc[4][4] = {};
    for (int kt = 0; kt <= it; kt++) {
        load_tile_T(As, Ph + (size_t)(it*64)*TT + kt*64, TT, tid);
        load_tile_D(Bs, Vh + (size_t)(kt*64)*DD, DD, tid);
        __syncthreads();
        mm64<false>(As, Bs, acc, tr4, tc4);
        __syncthreads();
    }
#pragma unroll
    for (int i = 0; i < 4; i++)
        *(float4*)&O2[(size_t)(it*64 + tr4 + i)*2048 + h*64 + tc4] =
            make_float4(acc[i][0], acc[i][1], acc[i][2], acc[i][3]);
}

// ---------------- beta ----------------
__global__ void beta_fix(const float* __restrict__ tmp, const float* __restrict__ bias,
                         float* __restrict__ betah) {
    int idx = blockIdx.x * blockDim.x + threadIdx.x;   // 32768
    int t = idx >> 5, hr = idx & 31;
    betah[hr*TT + t] = 2.f / (1.f + __expf(-(tmp[t*32 + hr] + bias[hr])));
}

// ---------------- conv + silu + rotation + normalize -> wdir[hr][t][d] ----------------
__global__ __launch_bounds__(64)
void wdir_kernel(const float* __restrict__ wraw, const float* __restrict__ conv_w,
                 const float* __restrict__ omega, const float* __restrict__ phi,
                 float* __restrict__ wdir) {
    int t = blockIdx.x, hr = blockIdx.y, d = threadIdx.x;
    int hkv = hr >> 1, r = hr & 1;
    int cA = hkv * 256 + (2*r) * 64 + d;
    int cB = cA + 64;
    float a = 0.f, b = 0.f;
#pragma unroll
    for (int i = 0; i < 3; i++) {
        int tt = t + i - 2;
        if (tt >= 0) {
            a += wraw[(size_t)tt * 4096 + cA] * conv_w[cA*3 + i];
            b += wraw[(size_t)tt * 4096 + cB] * conv_w[cB*3 + i];
        }
    }
    a = a / (1.f + expf(-a));
    b = b / (1.f + expf(-b));
    float th = omega[r] * (float)t + phi[r];
    float w = a * cosf(th) + b * sinf(th);
    float ss = w * w;
#pragma unroll
    for (int o = 16; o; o >>= 1) ss += __shfl_xor_sync(~0u, ss, o);
    __shared__ float sh[2];
    if ((d & 31) == 0) sh[d >> 5] = ss;
    __syncthreads();
    float tot = sh[0] + sh[1];
    wdir[((size_t)hr * TT + t) * HDIM + d] = w * rsqrtf(tot + 1e-6f);
}

// ---------------- driver ----------------
extern "C" void kernel_launch(void* const* d_in, const int* in_sizes, int n_in,
                              void* d_out, int out_size) {
    const float* x    = (const float*)d_in[0];
    const float* q_w  = (const float*)d_in[1];
    const float* k_w  = (const float*)d_in[2];
    const float* v_w  = (const float*)d_in[3];
    const float* w1   = (const float*)d_in[4];
    const float* w2   = (const float*)d_in[5];
    const float* cw   = (const float*)d_in[6];
    const float* btw  = (const float*)d_in[7];
    const float* btb  = (const float*)d_in[8];
    const float* ow   = (const float*)d_in[9];
    const float* omega= (const float*)d_in[10];
    const float* phi  = (const float*)d_in[11];
    float* out = (float*)d_out;

    float *pq,*pk,*pv,*pwlow,*pwraw,*pbtmp,*pbetah,*pwdir,*pMw,*pBR,*pQK,*pQW,*pTinv,*pO2;
    cudaGetSymbolAddress((void**)&pq,    g_q);
    cudaGetSymbolAddress((void**)&pk,    g_k);
    cudaGetSymbolAddress((void**)&pv,    g_v);
    cudaGetSymbolAddress((void**)&pwlow, g_wlow);
    cudaGetSymbolAddress((void**)&pwraw, g_wraw);
    cudaGetSymbolAddress((void**)&pbtmp, g_btmp);
    cudaGetSymbolAddress((void**)&pbetah,g_betah);
    cudaGetSymbolAddress((void**)&pwdir, g_wdir);
    cudaGetSymbolAddress((void**)&pMw,   g_Mw);
    cudaGetSymbolAddress((void**)&pBR,   g_BR);
    cudaGetSymbolAddress((void**)&pQK,   g_QK);
    cudaGetSymbolAddress((void**)&pQW,   g_QW);
    cudaGetSymbolAddress((void**)&pTinv, g_Tinv);
    cudaGetSymbolAddress((void**)&pO2,   g_O2);

    // projections
    gemm_abt<<<dim3(16,16), 256>>>(x, q_w, pq, 1024, 1024, 1024, 1024, 1024, 1024);
    gemm_abt<<<dim3(16,16), 256>>>(x, k_w, pk, 1024, 1024, 1024, 1024, 1024, 1024);
    gemm_abt<<<dim3(16,16), 256>>>(x, v_w, pv, 1024, 1024, 1024, 1024, 1024, 1024);
    gemm_abt<<<dim3(1,16),  256>>>(x, w1, pwlow, 1024, 32, 1024, 1024, 1024, 32);
    gemm_abt<<<dim3(64,16), 256>>>(pwlow, w2, pwraw, 1024, 4096, 32, 32, 32, 4096);
    gemm_abt<<<dim3(1,16),  256>>>(x, btw, pbtmp, 1024, 32, 1024, 1024, 1024, 32);
    beta_fix<<<128, 256>>>(pbtmp, btb, pbetah);
    wdir_kernel<<<dim3(1024, 32), 64>>>(pwraw, cw, omega, phi, pwdir);

    // per-head matrices
    head_gemm<<<dim3(16,16,32), 256>>>(pwdir,0,TT*HDIM,HDIM, pwdir,0,TT*HDIM,HDIM, pbetah, pMw, 1);
    head_gemm<<<dim3(16,16,32), 256>>>(pwdir,0,TT*HDIM,HDIM, pk,   1,64,     1024, pbetah, pBR, 1);
    head_gemm<<<dim3(16,16,32), 256>>>(pq,   1,64,     1024, pk,   1,64,     1024, nullptr, pQK, 2);
    head_gemm<<<dim3(16,16,32), 256>>>(pq,   1,64,     1024, pwdir,0,TT*HDIM,HDIM, nullptr, pQW, 2);

    // triangular solve (blocked)
    compute_tinv<<<dim3(16,32), 64>>>(pMw, pTinv);
    for (int ci = 0; ci < 16; ci++)
        solve_chunk<<<dim3(ci+1, 32), 256>>>(ci, pMw, pBR, pTinv);

    // attention
    logits_gemm<<<dim3(16,16,32), 256>>>(pQW, pBR, pQK);
    softmax_rows<<<dim3(1024,32), 128>>>(pQK);
    pv_gemm<<<dim3(16,32), 256>>>(pQK, pv, pO2);

    // output projection
    gemm_abt<<<dim3(16,16), 256>>>(pO2, ow, out, 1024, 1024, 2048, 2048, 2048, 1024);
}

// round 2
// speedup vs baseline: 1.0021x; 1.0021x over previous
#include <cuda_runtime.h>
#include <cuda_bf16.h>
#include <cstdint>

#define TT 1024
#define DD 1024
#define HDIM 64
#define NHEADS 32
#define ATT_SCALE 0.125f   // 64^-0.5
#define HEAD_SZ (1024*1024)

// ---------------- scratch (device globals; allocation-free) ----------------
__device__ float g_q[TT*DD];
__device__ float g_k[TT*DD];
__device__ float g_v[TT*DD];
__device__ float g_wlow[TT*32];
__device__ float g_wraw[TT*4096];
__device__ float g_btmp[TT*32];
__device__ float g_betah[NHEADS*TT];
__device__ float g_wdir[NHEADS*TT*HDIM];
__device__ float g_Mw[NHEADS*HEAD_SZ];   // 128 MB
__device__ float g_BR[NHEADS*HEAD_SZ];   // rhs -> Bmat in place
__device__ float g_QK[NHEADS*HEAD_SZ];   // qk -> logits -> p in place
__device__ float g_QW[NHEADS*HEAD_SZ];
__device__ float g_Tinv[NHEADS*16*64*64];
__device__ float g_O2[TT*2048];

// ---------------- tile helpers ----------------
// Load a 64x64 tile whose source is contiguous along k; store transposed S[k][m].
__device__ __forceinline__ void load_tile_T(float (*S)[64], const float* src, int ld, int tid) {
    int r  = tid >> 2;
    int kq = (tid & 3) * 4;
#pragma unroll
    for (int q = 0; q < 4; q++) {
        int kk = kq + q * 16;
        float4 t4 = *(const float4*)(src + (size_t)r * ld + kk);
        S[kk+0][r] = t4.x; S[kk+1][r] = t4.y; S[kk+2][r] = t4.z; S[kk+3][r] = t4.w;
    }
}
// Load a 64x64 tile contiguous along n; store direct S[k][n].
__device__ __forceinline__ void load_tile_D(float (*S)[64], const float* src, int ld, int tid) {
    int kb = tid >> 4;
    int n4 = (tid & 15) * 4;
#pragma unroll
    for (int q = 0; q < 4; q++) {
        int k = kb + q * 16;
        *(float4*)&S[k][n4] = *(const float4*)(src + (size_t)k * ld + n4);
    }
}

template<bool SUB>
__device__ __forceinline__ void mm64(const float (*As)[64], const float (*Bs)[64],
                                     float acc[4][4], int tr4, int tc4) {
#pragma unroll
    for (int kk = 0; kk < 64; kk++) {
        float4 a4 = *(const float4*)&As[kk][tr4];
        float4 b4 = *(const float4*)&Bs[kk][tc4];
        float a[4] = {a4.x, a4.y, a4.z, a4.w};
        float b[4] = {b4.x, b4.y, b4.z, b4.w};
#pragma unroll
        for (int i = 0; i < 4; i++)
#pragma unroll
            for (int j = 0; j < 4; j++) {
                if (SUB) acc[i][j] -= a[i] * b[j];
                else     acc[i][j] += a[i] * b[j];
            }
    }
}

// ---------------- generic C = A @ B^T (row-major), tile 64x64, BK=16 ----------------
__global__ __launch_bounds__(256)
void gemm_abt(const float* __restrict__ A, const float* __restrict__ B,
              float* __restrict__ C, int M, int N, int K,
              int lda, int ldb, int ldc) {
    __shared__ float As[16][64], Bs[16][64];
    int n0 = blockIdx.x * 64, m0 = blockIdx.y * 64;
    int tid = threadIdx.x;
    int r  = tid >> 2;
    int kq = (tid & 3) * 4;
    int tr4 = (tid >> 4) * 4, tc4 = (tid & 15) * 4;
    float acc[4][4] = {};
    for (int k0 = 0; k0 < K; k0 += 16) {
        float4 a4 = *(const float4*)(A + (size_t)(m0 + r) * lda + k0 + kq);
        As[kq+0][r]=a4.x; As[kq+1][r]=a4.y; As[kq+2][r]=a4.z; As[kq+3][r]=a4.w;
        if (n0 + r < N) {
            float4 b4 = *(const float4*)(B + (size_t)(n0 + r) * ldb + k0 + kq);
            Bs[kq+0][r]=b4.x; Bs[kq+1][r]=b4.y; Bs[kq+2][r]=b4.z; Bs[kq+3][r]=b4.w;
        } else {
            Bs[kq+0][r]=0.f; Bs[kq+1][r]=0.f; Bs[kq+2][r]=0.f; Bs[kq+3][r]=0.f;
        }
        __syncthreads();
#pragma unroll
        for (int kk = 0; kk < 16; kk++) {
            float4 a = *(const float4*)&As[kk][tr4];
            float4 b = *(const float4*)&Bs[kk][tc4];
            float av[4]={a.x,a.y,a.z,a.w}, bv[4]={b.x,b.y,b.z,b.w};
#pragma unroll
            for (int i=0;i<4;i++)
#pragma unroll
                for (int j=0;j<4;j++) acc[i][j] += av[i]*bv[j];
        }
        __syncthreads();
    }
#pragma unroll
    for (int i = 0; i < 4; i++)
#pragma unroll
        for (int j = 0; j < 4; j++) {
            int col = n0 + tc4 + j;
            if (col < N) C[(size_t)(m0 + tr4 + i) * ldc + col] = acc[i][j];
        }
}

// ---------------- per-head A @ B^T with causal masking ----------------
// mode 1: strict lower (col<row), mode 2: inclusive lower (col<=row). rowscale optional.
__global__ __launch_bounds__(256)
void head_gemm(const float* __restrict__ Abase, int a_shift, int a_per, int a_ld,
               const float* __restrict__ Bbase, int b_shift, int b_per, int b_ld,
               const float* __restrict__ rowscale, float* __restrict__ C, int mode) {
    int jt = blockIdx.x, it = blockIdx.y, h = blockIdx.z;
    if (jt > it) return;
    __shared__ float As[64][64], Bs[64][64];
    int tid = threadIdx.x;
    int tr4 = (tid >> 4) * 4, tc4 = (tid & 15) * 4;
    const float* A = Abase + (size_t)(a_shift ? (h >> 1) : h) * a_per + (size_t)(it*64) * a_ld;
    const float* B = Bbase + (size_t)(b_shift ? (h >> 1) : h) * b_per + (size_t)(jt*64) * b_ld;
    load_tile_T(As, A, a_ld, tid);
    load_tile_T(Bs, B, b_ld, tid);
    __syncthreads();
    float acc[4][4] = {};
    mm64<false>(As, Bs, acc, tr4, tc4);
    float* Ch = C + (size_t)h * HEAD_SZ;
#pragma unroll
    for (int i = 0; i < 4; i++) {
        int row = it*64 + tr4 + i;
        float sc = rowscale ? rowscale[h*TT + row] : 1.f;
        float o[4];
#pragma unroll
        for (int j = 0; j < 4; j++) {
            int col = jt*64 + tc4 + j;
            float v = acc[i][j] * sc;
            if (mode == 1 && col >= row) v = 0.f;
            if (mode == 2 && col >  row) v = 0.f;
            o[j] = v;
        }
        *(float4*)&Ch[(size_t)row*TT + jt*64 + tc4] = make_float4(o[0],o[1],o[2],o[3]);
    }
}

// ---------------- invert (I + L) for every 64x64 diagonal block ----------------
__global__ __launch_bounds__(64)
void compute_tinv(const float* __restrict__ Mw, float* __restrict__ Tinv) {
    __shared__ float L[64][65];
    __shared__ float X[64][65];
    int ch = blockIdx.x, h = blockIdx.y, c = threadIdx.x;
    const float* M = Mw + (size_t)h * HEAD_SZ + (size_t)(ch*64) * TT + ch*64;
    for (int r = 0; r < 64; r++) {
        L[r][c] = M[(size_t)r*TT + c];
        X[r][c] = (r == c) ? 1.f : 0.f;
    }
    __syncthreads();
    for (int r = 1; r < 64; r++) {
        if (c < r) {
            float acc = 0.f;
            for (int s = c; s < r; s++) acc += L[r][s] * X[s][c];
            X[r][c] = -acc;
        }
        __syncthreads();
    }
    float* out = Tinv + ((size_t)(h*16 + ch)) * 4096;
    for (int r = 0; r < 64; r++) out[r*64 + c] = X[r][c];
}

// ---------------- blocked forward substitution, chunk ci ----------------
// B[ci, jt] = Tinv_ci @ ( rhs[ci, jt] - sum_{s=jt..ci-1} Mw[ci, s] @ B[s, jt] )
__global__ __launch_bounds__(256)
void solve_chunk(int ci, const float* __restrict__ Mw,
                 float* __restrict__ BR, const float* __restrict__ Tinv) {
    int jt = blockIdx.x, h = blockIdx.y;
    __shared__ float As[64][64], Bs[64][64];
    int tid = threadIdx.x;
    int tr4 = (tid >> 4) * 4, tc4 = (tid & 15) * 4;
    const float* MwH = Mw + (size_t)h * HEAD_SZ;
    float* BRH = BR + (size_t)h * HEAD_SZ;
    float acc[4][4];
#pragma unroll
    for (int i = 0; i < 4; i++) {
        float4 v = *(const float4*)&BRH[(size_t)(ci*64 + tr4 + i)*TT + jt*64 + tc4];
        acc[i][0]=v.x; acc[i][1]=v.y; acc[i][2]=v.z; acc[i][3]=v.w;
    }
    for (int s = jt; s < ci; s++) {
        load_tile_T(As, MwH + (size_t)(ci*64)*TT + s*64, TT, tid);
        load_tile_D(Bs, BRH + (size_t)(s*64)*TT + jt*64, TT, tid);
        __syncthreads();
        mm64<true>(As, Bs, acc, tr4, tc4);
        __syncthreads();
    }
    // stage P into As, Tinv^T into Bs
#pragma unroll
    for (int i = 0; i < 4; i++)
        *(float4*)&As[tr4 + i][tc4] = make_float4(acc[i][0], acc[i][1], acc[i][2], acc[i][3]);
    load_tile_T(Bs, Tinv + ((size_t)(h*16 + ci)) * 4096, 64, tid);
    __syncthreads();
#pragma unroll
    for (int i=0;i<4;i++)
#pragma unroll
        for (int j=0;j<4;j++) acc[i][j] = 0.f;
    mm64<false>(Bs, As, acc, tr4, tc4);   // Bs[s][r]=Tinv[r][s], As[s][c]=P[s][c]
#pragma unroll
    for (int i = 0; i < 4; i++)
        *(float4*)&BRH[(size_t)(ci*64 + tr4 + i)*TT + jt*64 + tc4] =
            make_float4(acc[i][0], acc[i][1], acc[i][2], acc[i][3]);
}

// ---------------- logits = (qk - QW @ Bmat) * scale, causal tiles only ----------------
__global__ __launch_bounds__(256)
void logits_gemm(const float* __restrict__ QW, const float* __restrict__ BR,
                 float* __restrict__ QK) {
    int jt = blockIdx.x, it = blockIdx.y, h = blockIdx.z;
    if (jt > it) return;
    __shared__ float As[64][64], Bs[64][64];
    int tid = threadIdx.x;
    int tr4 = (tid >> 4) * 4, tc4 = (tid & 15) * 4;
    const float* QWh = QW + (size_t)h * HEAD_SZ;
    const float* BRh = BR + (size_t)h * HEAD_SZ;
    float* QKh = QK + (size_t)h * HEAD_SZ;
    float acc[4][4] = {};
    for (int kt = jt; kt <= it; kt++) {
        load_tile_T(As, QWh + (size_t)(it*64)*TT + kt*64, TT, tid);
        load_tile_D(Bs, BRh + (size_t)(kt*64)*TT + jt*64, TT, tid);
        __syncthreads();
        mm64<false>(As, Bs, acc, tr4, tc4);
        __syncthreads();
    }
#pragma unroll
    for (int i = 0; i < 4; i++) {
        size_t off = (size_t)(it*64 + tr4 + i)*TT + jt*64 + tc4;
        float4 q = *(const float4*)&QKh[off];
        *(float4*)&QKh[off] = make_float4((q.x - acc[i][0]) * ATT_SCALE,
                                          (q.y - acc[i][1]) * ATT_SCALE,
                                          (q.z - acc[i][2]) * ATT_SCALE,
                                          (q.w - acc[i][3]) * ATT_SCALE);
    }
}

// ---------------- causal row softmax, in place ----------------
__global__ __launch_bounds__(128)
void softmax_rows(float* __restrict__ P) {
    int i = blockIdx.x, h = blockIdx.y, tid = threadIdx.x;
    float* row = P + (size_t)h * HEAD_SZ + (size_t)i * TT;
    int n = i + 1;
    __shared__ float sh[4];
    float mx = -1e30f;
    for (int j = tid; j < n; j += 128) mx = fmaxf(mx, row[j]);
#pragma unroll
    for (int o = 16; o; o >>= 1) mx = fmaxf(mx, __shfl_xor_sync(~0u, mx, o));
    if ((tid & 31) == 0) sh[tid >> 5] = mx;
    __syncthreads();
    mx = fmaxf(fmaxf(sh[0], sh[1]), fmaxf(sh[2], sh[3]));
    __syncthreads();
    float sum = 0.f;
    for (int j = tid; j < n; j += 128) { float e = __expf(row[j] - mx); row[j] = e; sum += e; }
#pragma unroll
    for (int o = 16; o; o >>= 1) sum += __shfl_xor_sync(~0u, sum, o);
    if ((tid & 31) == 0) sh[tid >> 5] = sum;
    __syncthreads();
    sum = sh[0] + sh[1] + sh[2] + sh[3];
    float inv = 1.f / sum;
    for (int j = tid; j < n; j += 128) row[j] *= inv;
}

// ---------------- O2[i, h*64+d] = sum_{j<=i} P[i,j] * V[j, (h>>1)*64+d] ----------------
__global__ __launch_bounds__(256)
void pv_gemm(const float* __restrict__ P, const float* __restrict__ V,
             float* __restrict__ O2) {
    int it = blockIdx.x, h = blockIdx.y;
    __shared__ float As[64][64], Bs[64][64];
    int tid = threadIdx.x;
    int tr4 = (tid >> 4) * 4, tc4 = (tid & 15) * 4;
    const float* Ph = P + (size_t)h * HEAD_SZ;
    const float* Vh = V + (size_t)(h >> 1) * 64;
    float acc[4][4] = {};
    for (int kt = 0; kt <= it; kt++) {
        load_tile_T(As, Ph + (size_t)(it*64)*TT + kt*64, TT, tid);
        load_tile_D(Bs, Vh + (size_t)(kt*64)*DD, DD, tid);
        __syncthreads();
        mm64<false>(As, Bs, acc, tr4, tc4);
        __syncthreads();
    }
#pragma unroll
    for (int i = 0; i < 4; i++)
        *(float4*)&O2[(size_t)(it*64 + tr4 + i)*2048 + h*64 + tc4] =
            make_float4(acc[i][0], acc[i][1], acc[i][2], acc[i][3]);
}

// ---------------- beta ----------------
__global__ void beta_fix(const float* __restrict__ tmp, const float* __restrict__ bias,
                         float* __restrict__ betah) {
    int idx = blockIdx.x * blockDim.x + threadIdx.x;   // 32768
    int t = idx >> 5, hr = idx & 31;
    betah[hr*TT + t] = 2.f / (1.f + __expf(-(tmp[t*32 + hr] + bias[hr])));
}

// ---------------- conv + silu + rotation + normalize -> wdir[hr][t][d] ----------------
__global__ __launch_bounds__(64)
void wdir_kernel(const float* __restrict__ wraw, const float* __restrict__ conv_w,
                 const float* __restrict__ omega, const float* __restrict__ phi,
                 float* __restrict__ wdir) {
    int t = blockIdx.x, hr = blockIdx.y, d = threadIdx.x;
    int hkv = hr >> 1, r = hr & 1;
    int cA = hkv * 256 + (2*r) * 64 + d;
    int cB = cA + 64;
    float a = 0.f, b = 0.f;
#pragma unroll
    for (int i = 0; i < 3; i++) {
        int tt = t + i - 2;
        if (tt >= 0) {
            a += wraw[(size_t)tt * 4096 + cA] * conv_w[cA*3 + i];
            b += wraw[(size_t)tt * 4096 + cB] * conv_w[cB*3 + i];
        }
    }
    a = a / (1.f + expf(-a));
    b = b / (1.f + expf(-b));
    float th = omega[r] * (float)t + phi[r];
    float w = a * cosf(th) + b * sinf(th);
    float ss = w * w;
#pragma unroll
    for (int o = 16; o; o >>= 1) ss += __shfl_xor_sync(~0u, ss, o);
    __shared__ float sh[2];
    if ((d & 31) == 0) sh[d >> 5] = ss;
    __syncthreads();
    float tot = sh[0] + sh[1];
    wdir[((size_t)hr * TT + t) * HDIM + d] = w * rsqrtf(tot + 1e-6f);
}

// ---------------- driver ----------------
extern "C" void kernel_launch(void* const* d_in, const int* in_sizes, int n_in,
                              void* d_out, int out_size) {
    const float* x    = (const float*)d_in[0];
    const float* q_w  = (const float*)d_in[1];
    const float* k_w  = (const float*)d_in[2];
    const float* v_w  = (const float*)d_in[3];
    const float* w1   = (const float*)d_in[4];
    const float* w2   = (const float*)d_in[5];
    const float* cw   = (const float*)d_in[6];
    const float* btw  = (const float*)d_in[7];
    const float* btb  = (const float*)d_in[8];
    const float* ow   = (const float*)d_in[9];
    const float* omega= (const float*)d_in[10];
    const float* phi  = (const float*)d_in[11];
    float* out = (float*)d_out;

    float *pq,*pk,*pv,*pwlow,*pwraw,*pbtmp,*pbetah,*pwdir,*pMw,*pBR,*pQK,*pQW,*pTinv,*pO2;
    cudaGetSymbolAddress((void**)&pq,    g_q);
    cudaGetSymbolAddress((void**)&pk,    g_k);
    cudaGetSymbolAddress((void**)&pv,    g_v);
    cudaGetSymbolAddress((void**)&pwlow, g_wlow);
    cudaGetSymbolAddress((void**)&pwraw, g_wraw);
    cudaGetSymbolAddress((void**)&pbtmp, g_btmp);
    cudaGetSymbolAddress((void**)&pbetah,g_betah);
    cudaGetSymbolAddress((void**)&pwdir, g_wdir);
    cudaGetSymbolAddress((void**)&pMw,   g_Mw);
    cudaGetSymbolAddress((void**)&pBR,   g_BR);
    cudaGetSymbolAddress((void**)&pQK,   g_QK);
    cudaGetSymbolAddress((void**)&pQW,   g_QW);
    cudaGetSymbolAddress((void**)&pTinv, g_Tinv);
    cudaGetSymbolAddress((void**)&pO2,   g_O2);

    // projections
    gemm_abt<<<dim3(16,16), 256>>>(x, q_w, pq, 1024, 1024, 1024, 1024, 1024, 1024);
    gemm_abt<<<dim3(16,16), 256>>>(x, k_w, pk, 1024, 1024, 1024, 1024, 1024, 1024);
    gemm_abt<<<dim3(16,16), 256>>>(x, v_w, pv, 1024, 1024, 1024, 1024, 1024, 1024);
    gemm_abt<<<dim3(1,16),  256>>>(x, w1, pwlow, 1024, 32, 1024, 1024, 1024, 32);
    gemm_abt<<<dim3(64,16), 256>>>(pwlow, w2, pwraw, 1024, 4096, 32, 32, 32, 4096);
    gemm_abt<<<dim3(1,16),  256>>>(x, btw, pbtmp, 1024, 32, 1024, 1024, 1024, 32);
    beta_fix<<<128, 256>>>(pbtmp, btb, pbetah);
    wdir_kernel<<<dim3(1024, 32), 64>>>(pwraw, cw, omega, phi, pwdir);

    // per-head matrices
    head_gemm<<<dim3(16,16,32), 256>>>(pwdir,0,TT*HDIM,HDIM, pwdir,0,TT*HDIM,HDIM, pbetah, pMw, 1);
    head_gemm<<<dim3(16,16,32), 256>>>(pwdir,0,TT*HDIM,HDIM, pk,   1,64,     1024, pbetah, pBR, 1);
    head_gemm<<<dim3(16,16,32), 256>>>(pq,   1,64,     1024, pk,   1,64,     1024, nullptr, pQK, 2);
    head_gemm<<<dim3(16,16,32), 256>>>(pq,   1,64,     1024, pwdir,0,TT*HDIM,HDIM, nullptr, pQW, 2);

    // triangular solve (blocked)
    compute_tinv<<<dim3(16,32), 64>>>(pMw, pTinv);
    for (int ci = 0; ci < 16; ci++)
        solve_chunk<<<dim3(ci+1, 32), 256>>>(ci, pMw, pBR, pTinv);

    // attention
    logits_gemm<<<dim3(16,16,32), 256>>>(pQW, pBR, pQK);
    softmax_rows<<<dim3(1024,32), 128>>>(pQK);
    pv_gemm<<<dim3(16,32), 256>>>(pQK, pv, pO2);

    // output projection
    gemm_abt<<<dim3(16,16), 256>>>(pO2, ow, out, 1024, 1024, 2048, 2048, 2048, 1024);
}

// round 3
// speedup vs baseline: 1.4822x; 1.4791x over previous
#include <cuda_runtime.h>
#include <cuda_bf16.h>
#include <cstdint>

using bf16 = __nv_bfloat16;

#define TT 1024
#define HS 1048576
#define ATT_SCALE 0.125f

// ---------------- f32 scratch ----------------
__device__ float g_wlow[TT*32];
__device__ float g_wraw[TT*4096];
__device__ float g_btmp[TT*32];
__device__ float g_betah[32*TT];
__device__ float g_rhs[32*HS];
__device__ float g_QK [32*HS];

// ---------------- split (hi,lo) bf16 scratch ----------------
__device__ bf16 g_xh[1048576],  g_xl[1048576];
__device__ bf16 g_qwh[1048576], g_qwl[1048576];
__device__ bf16 g_kwh[1048576], g_kwl[1048576];
__device__ bf16 g_vwh[1048576], g_vwl[1048576];
__device__ bf16 g_owh[2097152], g_owl[2097152];
__device__ bf16 g_qh[1048576],  g_ql[1048576];
__device__ bf16 g_kh[1048576],  g_kl[1048576];
__device__ bf16 g_vh[1048576],  g_vl[1048576];
__device__ bf16 g_wdh[2097152], g_wdl[2097152];
__device__ bf16 g_Mwh[33554432], g_Mwl[33554432];
__device__ bf16 g_Bh [33554432], g_Bl [33554432];
__device__ bf16 g_QWh[33554432], g_QWl[33554432];
__device__ bf16 g_Ph [33554432], g_Pl [33554432];
__device__ bf16 g_Tvh[2097152],  g_Tvl[2097152];
__device__ bf16 g_O2h[2097152],  g_O2l[2097152];

// ---------------- primitives ----------------
__device__ __forceinline__ uint32_t sptr(const void* p) {
    return (uint32_t)__cvta_generic_to_shared(p);
}
__device__ __forceinline__ void ldsm4(uint32_t* r, uint32_t a) {
    asm volatile("ldmatrix.sync.aligned.m8n8.x4.shared.b16 {%0,%1,%2,%3}, [%4];"
        : "=r"(r[0]), "=r"(r[1]), "=r"(r[2]), "=r"(r[3]) : "r"(a));
}
__device__ __forceinline__ void ldsm4t(uint32_t* r, uint32_t a) {
    asm volatile("ldmatrix.sync.aligned.m8n8.x4.trans.shared.b16 {%0,%1,%2,%3}, [%4];"
        : "=r"(r[0]), "=r"(r[1]), "=r"(r[2]), "=r"(r[3]) : "r"(a));
}
__device__ __forceinline__ void mma_bf(float* c, const uint32_t* a, const uint32_t* b) {
    asm volatile(
        "mma.sync.aligned.m16n8k16.row.col.f32.bf16.bf16.f32 "
        "{%0,%1,%2,%3},{%4,%5,%6,%7},{%8,%9},{%0,%1,%2,%3};"
        : "+f"(c[0]), "+f"(c[1]), "+f"(c[2]), "+f"(c[3])
        : "r"(a[0]), "r"(a[1]), "r"(a[2]), "r"(a[3]), "r"(b[0]), "r"(b[1]));
}
__device__ __forceinline__ void st_split2(bf16* hi, bf16* lo, size_t off, float v0, float v1) {
    bf16 h0 = __float2bfloat16(v0), h1 = __float2bfloat16(v1);
    *(__nv_bfloat162*)(hi + off) = __halves2bfloat162(h0, h1);
    *(__nv_bfloat162*)(lo + off) = __halves2bfloat162(
        __float2bfloat16(v0 - __bfloat162float(h0)),
        __float2bfloat16(v1 - __bfloat162float(h1)));
}

// warp computes 32x32; acc[2 m16][4 n8][4]; 3-pass split mma (hh + hl + lh)
template<bool TRANSB>
__device__ __forceinline__ void mma_tile(float (&acc)[2][4][4],
    const bf16* sAh, const bf16* sAl, int SA, int arow, int ka0,
    const bf16* sBh, const bf16* sBl, int SB, int bcol, int kb0, int lane)
{
    uint32_t ah[2][4], al[2][4];
    {
        int r = arow + (lane & 15);
        int c = ka0 + ((lane >> 4) << 3);
        ldsm4(ah[0], sptr(sAh + r * SA + c));
        ldsm4(ah[1], sptr(sAh + (r + 16) * SA + c));
        ldsm4(al[0], sptr(sAl + r * SA + c));
        ldsm4(al[1], sptr(sAl + (r + 16) * SA + c));
    }
    uint32_t bh[4][2], bl[4][2];
    int m = lane >> 3, rr = lane & 7;
#pragma unroll
    for (int g = 0; g < 2; g++) {
        uint32_t t[4];
        if (!TRANSB) {
            int n  = bcol + g * 16 + ((m >> 1) << 3) + rr;
            int kk = kb0 + ((m & 1) << 3);
            ldsm4(t, sptr(sBh + n * SB + kk));
            bh[2*g][0]=t[0]; bh[2*g][1]=t[1]; bh[2*g+1][0]=t[2]; bh[2*g+1][1]=t[3];
            ldsm4(t, sptr(sBl + n * SB + kk));
            bl[2*g][0]=t[0]; bl[2*g][1]=t[1]; bl[2*g+1][0]=t[2]; bl[2*g+1][1]=t[3];
        } else {
            int kr = kb0 + ((m & 1) << 3) + rr;
            int nc = bcol + g * 16 + ((m >> 1) << 3);
            ldsm4t(t, sptr(sBh + kr * SB + nc));
            bh[2*g][0]=t[0]; bh[2*g][1]=t[1]; bh[2*g+1][0]=t[2]; bh[2*g+1][1]=t[3];
            ldsm4t(t, sptr(sBl + kr * SB + nc));
            bl[2*g][0]=t[0]; bl[2*g][1]=t[1]; bl[2*g+1][0]=t[2]; bl[2*g+1][1]=t[3];
        }
    }
#pragma unroll
    for (int mi = 0; mi < 2; mi++)
#pragma unroll
        for (int ni = 0; ni < 4; ni++) {
            mma_bf(acc[mi][ni], ah[mi], bh[ni]);
            mma_bf(acc[mi][ni], ah[mi], bl[ni]);
            mma_bf(acc[mi][ni], al[mi], bh[ni]);
        }
}

// stage rows x (c8*8) split pair into smem with given stride (256 threads)
__device__ __forceinline__ void stage2(bf16* dh, bf16* dl, int stride,
    const bf16* gh, const bf16* gl, int ld, int rows, int c8, int tid)
{
    for (int i = tid; i < rows * c8; i += 256) {
        int r = i / c8, c = (i - r * c8) * 8;
        *(uint4*)(dh + r * stride + c) = *(const uint4*)(gh + (size_t)r * ld + c);
        *(uint4*)(dl + r * stride + c) = *(const uint4*)(gl + (size_t)r * ld + c);
    }
}

// ---------------- elementwise split ----------------
__global__ __launch_bounds__(256)
void split_kernel(const float* __restrict__ in, bf16* __restrict__ hi,
                  bf16* __restrict__ lo, int n) {
    int i = blockIdx.x * 256 + threadIdx.x;
    if (i < n) {
        float v = in[i];
        bf16 h = __float2bfloat16(v);
        hi[i] = h;
        lo[i] = __float2bfloat16(v - __bfloat162float(h));
    }
}

// ---------------- dense C = A @ B^T, block tile 128x64 ----------------
__global__ __launch_bounds__(256)
void tc_dense(const bf16* __restrict__ Ah, const bf16* __restrict__ Al, int lda,
              const bf16* __restrict__ Bh, const bf16* __restrict__ Bl, int ldb,
              int K, bf16* __restrict__ Ch, bf16* __restrict__ Cl,
              float* __restrict__ Cf, int ldc)
{
    __shared__ __align__(16) bf16 sAh[128*40], sAl[128*40], sBh[64*40], sBl[64*40];
    int tid = threadIdx.x, lane = tid & 31, w = tid >> 5;
    int m0 = blockIdx.y * 128, n0 = blockIdx.x * 64;
    int arow = (w >> 1) * 32, bcol = (w & 1) * 32;
    float acc[2][4][4] = {};
    for (int k0 = 0; k0 < K; k0 += 32) {
        stage2(sAh, sAl, 40, Ah + (size_t)m0*lda + k0, Al + (size_t)m0*lda + k0, lda, 128, 4, tid);
        stage2(sBh, sBl, 40, Bh + (size_t)n0*ldb + k0, Bl + (size_t)n0*ldb + k0, ldb, 64, 4, tid);
        __syncthreads();
        mma_tile<false>(acc, sAh, sAl, 40, arow, 0,  sBh, sBl, 40, bcol, 0,  lane);
        mma_tile<false>(acc, sAh, sAl, 40, arow, 16, sBh, sBl, 40, bcol, 16, lane);
        __syncthreads();
    }
    int r0 = arow + (lane >> 2), c0 = bcol + (lane & 3) * 2;
#pragma unroll
    for (int mi = 0; mi < 2; mi++)
#pragma unroll
        for (int ni = 0; ni < 4; ni++)
#pragma unroll
            for (int hf = 0; hf < 2; hf++) {
                int row = m0 + r0 + mi * 16 + hf * 8;
                int col = n0 + c0 + ni * 8;
                float v0 = acc[mi][ni][hf*2], v1 = acc[mi][ni][hf*2+1];
                size_t off = (size_t)row * ldc + col;
                if (Cf) *(float2*)&Cf[off] = make_float2(v0, v1);
                else    st_split2(Ch, Cl, off, v0, v1);
            }
}

// ---------------- per-head C = A @ B^T with causal mask, K=64, tile 128x64 ----------------
__global__ __launch_bounds__(256)
void tc_head(const bf16* __restrict__ Abh, const bf16* __restrict__ Abl,
             int a_hdiv, size_t a_per, int lda,
             const bf16* __restrict__ Bbh, const bf16* __restrict__ Bbl,
             int b_hdiv, size_t b_per, int ldb,
             const float* __restrict__ rowscale, int mode,
             bf16* __restrict__ Ch, bf16* __restrict__ Cl, float* __restrict__ Cf)
{
    int jt = blockIdx.x, it = blockIdx.y, h = blockIdx.z;
    if (jt > 2 * it + 1) return;
    __shared__ __align__(16) bf16 sAh[128*40], sAl[128*40], sBh[64*40], sBl[64*40];
    int tid = threadIdx.x, lane = tid & 31, w = tid >> 5;
    int arow = (w >> 1) * 32, bcol = (w & 1) * 32;
    const bf16* Ahp = Abh + (size_t)(a_hdiv ? (h >> 1) : h) * a_per + (size_t)(it*128) * lda;
    const bf16* Alp = Abl + (size_t)(a_hdiv ? (h >> 1) : h) * a_per + (size_t)(it*128) * lda;
    const bf16* Bhp = Bbh + (size_t)(b_hdiv ? (h >> 1) : h) * b_per + (size_t)(jt*64) * ldb;
    const bf16* Blp = Bbl + (size_t)(b_hdiv ? (h >> 1) : h) * b_per + (size_t)(jt*64) * ldb;
    float acc[2][4][4] = {};
#pragma unroll
    for (int k0 = 0; k0 < 64; k0 += 32) {
        stage2(sAh, sAl, 40, Ahp + k0, Alp + k0, lda, 128, 4, tid);
        stage2(sBh, sBl, 40, Bhp + k0, Blp + k0, ldb, 64, 4, tid);
        __syncthreads();
        mma_tile<false>(acc, sAh, sAl, 40, arow, 0,  sBh, sBl, 40, bcol, 0,  lane);
        mma_tile<false>(acc, sAh, sAl, 40, arow, 16, sBh, sBl, 40, bcol, 16, lane);
        __syncthreads();
    }
    int r0 = arow + (lane >> 2), c0 = bcol + (lane & 3) * 2;
    size_t hb = (size_t)h * HS;
#pragma unroll
    for (int mi = 0; mi < 2; mi++)
#pragma unroll
        for (int ni = 0; ni < 4; ni++)
#pragma unroll
            for (int hf = 0; hf < 2; hf++) {
                int row = it*128 + r0 + mi * 16 + hf * 8;
                int col = jt*64 + c0 + ni * 8;
                float v0 = acc[mi][ni][hf*2], v1 = acc[mi][ni][hf*2+1];
                float sc = rowscale ? rowscale[h * TT + row] : 1.f;
                v0 *= sc; v1 *= sc;
                if (mode == 1) { if (col   >= row) v0 = 0.f;
                                 if (col+1 >= row) v1 = 0.f; }
                else           { if (col   >  row) v0 = 0.f;
                                 if (col+1 >  row) v1 = 0.f; }
                size_t off = hb + (size_t)row * TT + col;
                if (Cf) *(float2*)&Cf[off] = make_float2(v0, v1);
                else    st_split2(Ch, Cl, off, v0, v1);
            }
}

// ---------------- invert (I + L) per 64x64 diagonal block ----------------
__global__ __launch_bounds__(64)
void compute_tinv() {
    __shared__ float L[64][65];
    __shared__ float X[64][65];
    int ch = blockIdx.x, h = blockIdx.y, c = threadIdx.x;
    size_t base = (size_t)h * HS + (size_t)(ch*64) * TT + ch*64;
    for (int r = 0; r < 64; r++) {
        L[r][c] = __bfloat162float(g_Mwh[base + (size_t)r*TT + c]) +
                  __bfloat162float(g_Mwl[base + (size_t)r*TT + c]);
        X[r][c] = (r == c) ? 1.f : 0.f;
    }
    __syncthreads();
    for (int r = 1; r < 64; r++) {
        if (c < r) {
            float acc = 0.f;
            for (int s = c; s < r; s++) acc += L[r][s] * X[s][c];
            X[r][c] = -acc;
        }
        __syncthreads();
    }
    size_t ob = ((size_t)(h*16 + ch)) * 4096;
    for (int r = 0; r < 64; r++) {
        float v = X[r][c];
        bf16 hh = __float2bfloat16(v);
        g_Tvh[ob + r*64 + c] = hh;
        g_Tvl[ob + r*64 + c] = __float2bfloat16(v - __bfloat162float(hh));
    }
}

// ---------------- blocked forward substitution, chunk ci; tile 64x128 ----------------
__global__ __launch_bounds__(256)
void tc_solve(int ci) {
    __shared__ __align__(16) char raw[45056];
    bf16* sMh = (bf16*)(raw);              // 64*40
    bf16* sMl = (bf16*)(raw + 5120);
    bf16* sKh = (bf16*)(raw + 10240);      // 32*136 (B chunk, T-form)
    bf16* sKl = (bf16*)(raw + 18944);
    bf16* sPh = (bf16*)(raw);              // 64*136 (phase 2)
    bf16* sPl = (bf16*)(raw + 17408);
    bf16* sTh = (bf16*)(raw + 34816);      // 64*40
    bf16* sTl = (bf16*)(raw + 39936);

    int jb = blockIdx.x, h = blockIdx.y;
    int tid = threadIdx.x, lane = tid & 31, w = tid >> 5;
    int arow = (w >> 2) * 32, bcol = (w & 3) * 32;
    size_t hb = (size_t)h * HS;
    int r0 = arow + (lane >> 2), c0 = bcol + (lane & 3) * 2;

    float acc[2][4][4];
#pragma unroll
    for (int mi = 0; mi < 2; mi++)
#pragma unroll
        for (int ni = 0; ni < 4; ni++)
#pragma unroll
            for (int hf = 0; hf < 2; hf++) {
                float2 v = *(const float2*)&g_rhs[hb +
                    (size_t)(ci*64 + r0 + mi*16 + hf*8) * TT + jb*128 + c0 + ni*8];
                acc[mi][ni][hf*2]   = -v.x;
                acc[mi][ni][hf*2+1] = -v.y;
            }

    for (int s = 2 * jb; s < ci; s++) {
#pragma unroll
        for (int kc = 0; kc < 64; kc += 32) {
            stage2(sMh, sMl, 40,
                   g_Mwh + hb + (size_t)(ci*64) * TT + s*64 + kc,
                   g_Mwl + hb + (size_t)(ci*64) * TT + s*64 + kc, TT, 64, 4, tid);
            stage2(sKh, sKl, 136,
                   g_Bh + hb + (size_t)(s*64 + kc) * TT + jb*128,
                   g_Bl + hb + (size_t)(s*64 + kc) * TT + jb*128, TT, 32, 16, tid);
            __syncthreads();
            mma_tile<true>(acc, sMh, sMl, 40, arow, 0,  sKh, sKl, 136, bcol, 0,  lane);
            mma_tile<true>(acc, sMh, sMl, 40, arow, 16, sKh, sKl, 136, bcol, 16, lane);
            __syncthreads();
        }
    }

    // P = -(acc) into smem split
#pragma unroll
    for (int mi = 0; mi < 2; mi++)
#pragma unroll
        for (int ni = 0; ni < 4; ni++)
#pragma unroll
            for (int hf = 0; hf < 2; hf++) {
                int r = r0 + mi*16 + hf*8, c = c0 + ni*8;
                st_split2(sPh, sPl, (size_t)r*136 + c,
                          -acc[mi][ni][hf*2], -acc[mi][ni][hf*2+1]);
            }

    // out = Tinv @ P
#pragma unroll
    for (int mi = 0; mi < 2; mi++)
#pragma unroll
        for (int ni = 0; ni < 4; ni++)
#pragma unroll
            for (int e = 0; e < 4; e++) acc[mi][ni][e] = 0.f;

    size_t tb = ((size_t)(h*16 + ci)) * 4096;
#pragma unroll
    for (int kc = 0; kc < 64; kc += 32) {
        stage2(sTh, sTl, 40, g_Tvh + tb + kc, g_Tvl + tb + kc, 64, 64, 4, tid);
        __syncthreads();
        mma_tile<true>(acc, sTh, sTl, 40, arow, 0,  sPh, sPl, 136, bcol, kc,      lane);
        mma_tile<true>(acc, sTh, sTl, 40, arow, 16, sPh, sPl, 136, bcol, kc + 16, lane);
        __syncthreads();
    }
#pragma unroll
    for (int mi = 0; mi < 2; mi++)
#pragma unroll
        for (int ni = 0; ni < 4; ni++)
#pragma unroll
            for (int hf = 0; hf < 2; hf++) {
                int row = ci*64 + r0 + mi*16 + hf*8;
                int col = jb*128 + c0 + ni*8;
                st_split2(g_Bh, g_Bl, hb + (size_t)row*TT + col,
                          acc[mi][ni][hf*2], acc[mi][ni][hf*2+1]);
            }
}

// ---------------- logits = (qk - QW @ Bmat) * scale, tile 128x64 ----------------
__global__ __launch_bounds__(256)
void tc_logits() {
    int jt = blockIdx.x, it = blockIdx.y, h = blockIdx.z;
    if (jt > 2 * it + 1) return;
    __shared__ __align__(16) bf16 sAh[128*40], sAl[128*40], sBh[32*72], sBl[32*72];
    int tid = threadIdx.x, lane = tid & 31, w = tid >> 5;
    int arow = (w >> 1) * 32, bcol = (w & 1) * 32;
    size_t hb = (size_t)h * HS;
    float acc[2][4][4] = {};
    int kb_hi = 2 * it + 1;
    for (int kb = jt; kb <= kb_hi; kb++) {
#pragma unroll
        for (int kc = 0; kc < 64; kc += 32) {
            stage2(sAh, sAl, 40,
                   g_QWh + hb + (size_t)(it*128) * TT + kb*64 + kc,
                   g_QWl + hb + (size_t)(it*128) * TT + kb*64 + kc, TT, 128, 4, tid);
            stage2(sBh, sBl, 72,
                   g_Bh + hb + (size_t)(kb*64 + kc) * TT + jt*64,
                   g_Bl + hb + (size_t)(kb*64 + kc) * TT + jt*64, TT, 32, 8, tid);
            __syncthreads();
            mma_tile<true>(acc, sAh, sAl, 40, arow, 0,  sBh, sBl, 72, bcol, 0,  lane);
            mma_tile<true>(acc, sAh, sAl, 40, arow, 16, sBh, sBl, 72, bcol, 16, lane);
            __syncthreads();
        }
    }
    int r0 = arow + (lane >> 2), c0 = bcol + (lane & 3) * 2;
#pragma unroll
    for (int mi = 0; mi < 2; mi++)
#pragma unroll
        for (int ni = 0; ni < 4; ni++)
#pragma unroll
            for (int hf = 0; hf < 2; hf++) {
                int row = it*128 + r0 + mi*16 + hf*8;
                int col = jt*64 + c0 + ni*8;
                size_t off = hb + (size_t)row*TT + col;
                float2 q = *(const float2*)&g_QK[off];
                *(float2*)&g_QK[off] = make_float2(
                    (q.x - acc[mi][ni][hf*2])   * ATT_SCALE,
                    (q.y - acc[mi][ni][hf*2+1]) * ATT_SCALE);
            }
}

// ---------------- causal row softmax -> split P (zeros above diag) ----------------
__global__ __launch_bounds__(128)
void softmax_rows() {
    int i = blockIdx.x, h = blockIdx.y, tid = threadIdx.x;
    float* row = g_QK + (size_t)h * HS + (size_t)i * TT;
    bf16* ph = g_Ph + (size_t)h * HS + (size_t)i * TT;
    bf16* pl = g_Pl + (size_t)h * HS + (size_t)i * TT;
    int n = i + 1;
    __shared__ float sh[4];
    float mx = -1e30f;
    for (int j = tid; j < n; j += 128) mx = fmaxf(mx, row[j]);
#pragma unroll
    for (int o = 16; o; o >>= 1) mx = fmaxf(mx, __shfl_xor_sync(~0u, mx, o));
    if ((tid & 31) == 0) sh[tid >> 5] = mx;
    __syncthreads();
    mx = fmaxf(fmaxf(sh[0], sh[1]), fmaxf(sh[2], sh[3]));
    __syncthreads();
    float sum = 0.f;
    for (int j = tid; j < n; j += 128) { float e = __expf(row[j] - mx); row[j] = e; sum += e; }
#pragma unroll
    for (int o = 16; o; o >>= 1) sum += __shfl_xor_sync(~0u, sum, o);
    if ((tid & 31) == 0) sh[tid >> 5] = sum;
    __syncthreads();
    sum = sh[0] + sh[1] + sh[2] + sh[3];
    float inv = 1.f / sum;
    for (int j = tid; j < TT; j += 128) {
        float p = (j < n) ? row[j] * inv : 0.f;
        bf16 hh = __float2bfloat16(p);
        ph[j] = hh;
        pl[j] = __float2bfloat16(p - __bfloat162float(hh));
    }
}

// ---------------- O2 = P @ V per head, tile 128x64 ----------------
__global__ __launch_bounds__(256)
void tc_pv() {
    int it = blockIdx.x, h = blockIdx.y;
    __shared__ __align__(16) bf16 sAh[128*40], sAl[128*40], sBh[32*72], sBl[32*72];
    int tid = threadIdx.x, lane = tid & 31, w = tid >> 5;
    int arow = (w >> 1) * 32, bcol = (w & 1) * 32;
    size_t hb = (size_t)h * HS;
    const bf16* vh = g_vh + (size_t)(h >> 1) * 64;
    const bf16* vl = g_vl + (size_t)(h >> 1) * 64;
    float acc[2][4][4] = {};
    int kb_hi = 2 * it + 1;
    for (int kb = 0; kb <= kb_hi; kb++) {
#pragma unroll
        for (int kc = 0; kc < 64; kc += 32) {
            stage2(sAh, sAl, 40,
                   g_Ph + hb + (size_t)(it*128) * TT + kb*64 + kc,
                   g_Pl + hb + (size_t)(it*128) * TT + kb*64 + kc, TT, 128, 4, tid);
            stage2(sBh, sBl, 72,
                   vh + (size_t)(kb*64 + kc) * 1024,
                   vl + (size_t)(kb*64 + kc) * 1024, 1024, 32, 8, tid);
            __syncthreads();
            mma_tile<true>(acc, sAh, sAl, 40, arow, 0,  sBh, sBl, 72, bcol, 0,  lane);
            mma_tile<true>(acc, sAh, sAl, 40, arow, 16, sBh, sBl, 72, bcol, 16, lane);
            __syncthreads();
        }
    }
    int r0 = arow + (lane >> 2), c0 = bcol + (lane & 3) * 2;
#pragma unroll
    for (int mi = 0; mi < 2; mi++)
#pragma unroll
        for (int ni = 0; ni < 4; ni++)
#pragma unroll
            for (int hf = 0; hf < 2; hf++) {
                int row = it*128 + r0 + mi*16 + hf*8;
                int col = c0 + ni*8;
                st_split2(g_O2h, g_O2l, (size_t)row * 2048 + h*64 + col,
                          acc[mi][ni][hf*2], acc[mi][ni][hf*2+1]);
            }
}

// ---------------- small fp32 GEMM (low-rank / beta paths) ----------------
__global__ __launch_bounds__(256)
void gemm_abt(const float* __restrict__ A, const float* __restrict__ B,
              float* __restrict__ C, int M, int N, int K,
              int lda, int ldb, int ldc) {
    __shared__ float As[16][64], Bs[16][64];
    int n0 = blockIdx.x * 64, m0 = blockIdx.y * 64;
    int tid = threadIdx.x;
    int r  = tid >> 2;
    int kq = (tid & 3) * 4;
    int tr4 = (tid >> 4) * 4, tc4 = (tid & 15) * 4;
    float acc[4][4] = {};
    for (int k0 = 0; k0 < K; k0 += 16) {
        float4 a4 = *(const float4*)(A + (size_t)(m0 + r) * lda + k0 + kq);
        As[kq+0][r]=a4.x; As[kq+1][r]=a4.y; As[kq+2][r]=a4.z; As[kq+3][r]=a4.w;
        if (n0 + r < N) {
            float4 b4 = *(const float4*)(B + (size_t)(n0 + r) * ldb + k0 + kq);
            Bs[kq+0][r]=b4.x; Bs[kq+1][r]=b4.y; Bs[kq+2][r]=b4.z; Bs[kq+3][r]=b4.w;
        } else {
            Bs[kq+0][r]=0.f; Bs[kq+1][r]=0.f; Bs[kq+2][r]=0.f; Bs[kq+3][r]=0.f;
        }
        __syncthreads();
#pragma unroll
        for (int kk = 0; kk < 16; kk++) {
            float4 a = *(const float4*)&As[kk][tr4];
            float4 b = *(const float4*)&Bs[kk][tc4];
            float av[4]={a.x,a.y,a.z,a.w}, bv[4]={b.x,b.y,b.z,b.w};
#pragma unroll
            for (int i=0;i<4;i++)
#pragma unroll
                for (int j=0;j<4;j++) acc[i][j] += av[i]*bv[j];
        }
        __syncthreads();
    }
#pragma unroll
    for (int i = 0; i < 4; i++)
#pragma unroll
        for (int j = 0; j < 4; j++) {
            int col = n0 + tc4 + j;
            if (col < N) C[(size_t)(m0 + tr4 + i) * ldc + col] = acc[i][j];
        }
}

__global__ void beta_fix(const float* __restrict__ tmp, const float* __restrict__ bias,
                         float* __restrict__ betah) {
    int idx = blockIdx.x * blockDim.x + threadIdx.x;
    int t = idx >> 5, hr = idx & 31;
    betah[hr*TT + t] = 2.f / (1.f + __expf(-(tmp[t*32 + hr] + bias[hr])));
}

__global__ __launch_bounds__(64)
void wdir_kernel(const float* __restrict__ wraw, const float* __restrict__ conv_w,
                 const float* __restrict__ omega, const float* __restrict__ phi) {
    int t = blockIdx.x, hr = blockIdx.y, d = threadIdx.x;
    int hkv = hr >> 1, r = hr & 1;
    int cA = hkv * 256 + (2*r) * 64 + d;
    int cB = cA + 64;
    float a = 0.f, b = 0.f;
#pragma unroll
    for (int i = 0; i < 3; i++) {
        int tt = t + i - 2;
        if (tt >= 0) {
            a += wraw[(size_t)tt * 4096 + cA] * conv_w[cA*3 + i];
            b += wraw[(size_t)tt * 4096 + cB] * conv_w[cB*3 + i];
        }
    }
    a = a / (1.f + expf(-a));
    b = b / (1.f + expf(-b));
    float th = omega[r] * (float)t + phi[r];
    float w = a * cosf(th) + b * sinf(th);
    float ss = w * w;
#pragma unroll
    for (int o = 16; o; o >>= 1) ss += __shfl_xor_sync(~0u, ss, o);
    __shared__ float sh[2];
    if ((d & 31) == 0) sh[d >> 5] = ss;
    __syncthreads();
    float tot = sh[0] + sh[1];
    float val = w * rsqrtf(tot + 1e-6f);
    size_t off = ((size_t)hr * TT + t) * 64 + d;
    bf16 hh = __float2bfloat16(val);
    g_wdh[off] = hh;
    g_wdl[off] = __float2bfloat16(val - __bfloat162float(hh));
}

// ---------------- driver ----------------
extern "C" void kernel_launch(void* const* d_in, const int* in_sizes, int n_in,
                              void* d_out, int out_size) {
    const float* x    = (const float*)d_in[0];
    const float* q_w  = (const float*)d_in[1];
    const float* k_w  = (const float*)d_in[2];
    const float* v_w  = (const float*)d_in[3];
    const float* w1   = (const float*)d_in[4];
    const float* w2   = (const float*)d_in[5];
    const float* cw   = (const float*)d_in[6];
    const float* btw  = (const float*)d_in[7];
    const float* btb  = (const float*)d_in[8];
    const float* ow   = (const float*)d_in[9];
    const float* omega= (const float*)d_in[10];
    const float* phi  = (const float*)d_in[11];
    float* out = (float*)d_out;

    float *pwlow,*pwraw,*pbtmp,*pbetah,*pQK,*prhs;
    bf16 *pxh,*pxl,*pqwh,*pqwl,*pkwh,*pkwl,*pvwh,*pvwl,*powh,*powl;
    bf16 *pqh,*pql,*pkh,*pkl,*pvh,*pvl,*pwdh,*pwdl;
    bf16 *pMwh,*pMwl,*pQWh,*pQWl,*pO2h,*pO2l;
    cudaGetSymbolAddress((void**)&pwlow, g_wlow);
    cudaGetSymbolAddress((void**)&pwraw, g_wraw);
    cudaGetSymbolAddress((void**)&pbtmp, g_btmp);
    cudaGetSymbolAddress((void**)&pbetah,g_betah);
    cudaGetSymbolAddress((void**)&pQK,   g_QK);
    cudaGetSymbolAddress((void**)&prhs,  g_rhs);
    cudaGetSymbolAddress((void**)&pxh,  g_xh);  cudaGetSymbolAddress((void**)&pxl,  g_xl);
    cudaGetSymbolAddress((void**)&pqwh, g_qwh); cudaGetSymbolAddress((void**)&pqwl, g_qwl);
    cudaGetSymbolAddress((void**)&pkwh, g_kwh); cudaGetSymbolAddress((void**)&pkwl, g_kwl);
    cudaGetSymbolAddress((void**)&pvwh, g_vwh); cudaGetSymbolAddress((void**)&pvwl, g_vwl);
    cudaGetSymbolAddress((void**)&powh, g_owh); cudaGetSymbolAddress((void**)&powl, g_owl);
    cudaGetSymbolAddress((void**)&pqh,  g_qh);  cudaGetSymbolAddress((void**)&pql,  g_ql);
    cudaGetSymbolAddress((void**)&pkh,  g_kh);  cudaGetSymbolAddress((void**)&pkl,  g_kl);
    cudaGetSymbolAddress((void**)&pvh,  g_vh);  cudaGetSymbolAddress((void**)&pvl,  g_vl);
    cudaGetSymbolAddress((void**)&pwdh, g_wdh); cudaGetSymbolAddress((void**)&pwdl, g_wdl);
    cudaGetSymbolAddress((void**)&pMwh, g_Mwh); cudaGetSymbolAddress((void**)&pMwl, g_Mwl);
    cudaGetSymbolAddress((void**)&pQWh, g_QWh); cudaGetSymbolAddress((void**)&pQWl, g_QWl);
    cudaGetSymbolAddress((void**)&pO2h, g_O2h); cudaGetSymbolAddress((void**)&pO2l, g_O2l);

    // splits
    split_kernel<<<4096, 256>>>(x,   pxh,  pxl,  1048576);
    split_kernel<<<4096, 256>>>(q_w, pqwh, pqwl, 1048576);
    split_kernel<<<4096, 256>>>(k_w, pkwh, pkwl, 1048576);
    split_kernel<<<4096, 256>>>(v_w, pvwh, pvwl, 1048576);
    split_kernel<<<8192, 256>>>(ow,  powh, powl, 2097152);

    // low-rank / beta paths (fp32)
    gemm_abt<<<dim3(1,16),  256>>>(x, w1, pwlow, 1024, 32, 1024, 1024, 1024, 32);
    gemm_abt<<<dim3(64,16), 256>>>(pwlow, w2, pwraw, 1024, 4096, 32, 32, 32, 4096);
    gemm_abt<<<dim3(1,16),  256>>>(x, btw, pbtmp, 1024, 32, 1024, 1024, 1024, 32);
    beta_fix<<<128, 256>>>(pbtmp, btb, pbetah);
    wdir_kernel<<<dim3(1024, 32), 64>>>(pwraw, cw, omega, phi);

    // projections (tensor core, split output)
    tc_dense<<<dim3(16,8), 256>>>(pxh, pxl, 1024, pqwh, pqwl, 1024, 1024, pqh, pql, nullptr, 1024);
    tc_dense<<<dim3(16,8), 256>>>(pxh, pxl, 1024, pkwh, pkwl, 1024, 1024, pkh, pkl, nullptr, 1024);
    tc_dense<<<dim3(16,8), 256>>>(pxh, pxl, 1024, pvwh, pvwl, 1024, 1024, pvh, pvl, nullptr, 1024);

    // per-head matrices
    tc_head<<<dim3(16,8,32), 256>>>(pwdh, pwdl, 0, 65536, 64, pwdh, pwdl, 0, 65536, 64,
                                    pbetah, 1, pMwh, pMwl, nullptr);              // Mw (split)
    tc_head<<<dim3(16,8,32), 256>>>(pwdh, pwdl, 0, 65536, 64, pkh, pkl, 1, 64, 1024,
                                    pbetah, 1, nullptr, nullptr, prhs);           // rhs (f32)
    tc_head<<<dim3(16,8,32), 256>>>(pqh, pql, 1, 64, 1024, pkh, pkl, 1, 64, 1024,
                                    nullptr, 2, nullptr, nullptr, pQK);           // QK (f32)
    tc_head<<<dim3(16,8,32), 256>>>(pqh, pql, 1, 64, 1024, pwdh, pwdl, 0, 65536, 64,
                                    nullptr, 2, pQWh, pQWl, nullptr);             // QW (split)

    // triangular solve
    compute_tinv<<<dim3(16,32), 64>>>();
    for (int ci = 0; ci < 16; ci++)
        tc_solve<<<dim3(ci/2 + 1, 32), 256>>>(ci);

    // attention
    tc_logits<<<dim3(16,8,32), 256>>>();
    softmax_rows<<<dim3(1024,32), 128>>>();
    tc_pv<<<dim3(8,32), 256>>>();

    // output projection
    tc_dense<<<dim3(16,8), 256>>>(pO2h, pO2l, 2048, powh, powl, 2048, 2048,
                                  nullptr, nullptr, out, 1024);
}

// round 4
// speedup vs baseline: 1.4880x; 1.0039x over previous
#include <cuda_runtime.h>
#include <cuda_bf16.h>
#include <cstdint>

using bf16 = __nv_bfloat16;

#define TT 1024
#define HS 1048576
#define ATT_SCALE 0.125f

// ---------------- f32 scratch ----------------
__device__ float g_wlow[TT*32];
__device__ float g_wraw[TT*4096];
__device__ float g_btmp[TT*32];
__device__ float g_betah[32*TT];
__device__ float g_rhs[32*HS];
__device__ float g_QK [32*HS];

// ---------------- split (hi,lo) bf16 scratch ----------------
__device__ bf16 g_xh[1048576],  g_xl[1048576];
__device__ bf16 g_qwh[1048576], g_qwl[1048576];
__device__ bf16 g_kwh[1048576], g_kwl[1048576];
__device__ bf16 g_vwh[1048576], g_vwl[1048576];
__device__ bf16 g_owh[2097152], g_owl[2097152];
__device__ bf16 g_qh[1048576],  g_ql[1048576];
__device__ bf16 g_kh[1048576],  g_kl[1048576];
__device__ bf16 g_vh[1048576],  g_vl[1048576];
__device__ bf16 g_wdh[2097152], g_wdl[2097152];
__device__ bf16 g_Mwh[33554432], g_Mwl[33554432];
__device__ bf16 g_Bh [33554432], g_Bl [33554432];
__device__ bf16 g_QWh[33554432], g_QWl[33554432];
__device__ bf16 g_Ph [33554432], g_Pl [33554432];
__device__ bf16 g_Tvh[2097152],  g_Tvl[2097152];
__device__ bf16 g_O2h[2097152],  g_O2l[2097152];

// ---------------- primitives ----------------
__device__ __forceinline__ uint32_t sptr(const void* p) {
    return (uint32_t)__cvta_generic_to_shared(p);
}
__device__ __forceinline__ void ldsm4(uint32_t* r, uint32_t a) {
    asm volatile("ldmatrix.sync.aligned.m8n8.x4.shared.b16 {%0,%1,%2,%3}, [%4];"
        : "=r"(r[0]), "=r"(r[1]), "=r"(r[2]), "=r"(r[3]) : "r"(a));
}
__device__ __forceinline__ void ldsm4t(uint32_t* r, uint32_t a) {
    asm volatile("ldmatrix.sync.aligned.m8n8.x4.trans.shared.b16 {%0,%1,%2,%3}, [%4];"
        : "=r"(r[0]), "=r"(r[1]), "=r"(r[2]), "=r"(r[3]) : "r"(a));
}
__device__ __forceinline__ void mma_bf(float* c, const uint32_t* a, const uint32_t* b) {
    asm volatile(
        "mma.sync.aligned.m16n8k16.row.col.f32.bf16.bf16.f32 "
        "{%0,%1,%2,%3},{%4,%5,%6,%7},{%8,%9},{%0,%1,%2,%3};"
        : "+f"(c[0]), "+f"(c[1]), "+f"(c[2]), "+f"(c[3])
        : "r"(a[0]), "r"(a[1]), "r"(a[2]), "r"(a[3]), "r"(b[0]), "r"(b[1]));
}
__device__ __forceinline__ void st_split2(bf16* hi, bf16* lo, size_t off, float v0, float v1) {
    bf16 h0 = __float2bfloat16(v0), h1 = __float2bfloat16(v1);
    *(__nv_bfloat162*)(hi + off) = __halves2bfloat162(h0, h1);
    *(__nv_bfloat162*)(lo + off) = __halves2bfloat162(
        __float2bfloat16(v0 - __bfloat162float(h0)),
        __float2bfloat16(v1 - __bfloat162float(h1)));
}

// warp computes 32x32; acc[2 m16][4 n8][4]; 3-pass split mma (hh + hl + lh)
template<bool TRANSB>
__device__ __forceinline__ void mma_tile(float (&acc)[2][4][4],
    const bf16* sAh, const bf16* sAl, int SA, int arow, int ka0,
    const bf16* sBh, const bf16* sBl, int SB, int bcol, int kb0, int lane)
{
    uint32_t ah[2][4], al[2][4];
    {
        int r = arow + (lane & 15);
        int c = ka0 + ((lane >> 4) << 3);
        ldsm4(ah[0], sptr(sAh + r * SA + c));
        ldsm4(ah[1], sptr(sAh + (r + 16) * SA + c));
        ldsm4(al[0], sptr(sAl + r * SA + c));
        ldsm4(al[1], sptr(sAl + (r + 16) * SA + c));
    }
    uint32_t bh[4][2], bl[4][2];
    int m = lane >> 3, rr = lane & 7;
#pragma unroll
    for (int g = 0; g < 2; g++) {
        uint32_t t[4];
        if (!TRANSB) {
            int n  = bcol + g * 16 + ((m >> 1) << 3) + rr;
            int kk = kb0 + ((m & 1) << 3);
            ldsm4(t, sptr(sBh + n * SB + kk));
            bh[2*g][0]=t[0]; bh[2*g][1]=t[1]; bh[2*g+1][0]=t[2]; bh[2*g+1][1]=t[3];
            ldsm4(t, sptr(sBl + n * SB + kk));
            bl[2*g][0]=t[0]; bl[2*g][1]=t[1]; bl[2*g+1][0]=t[2]; bl[2*g+1][1]=t[3];
        } else {
            int kr = kb0 + ((m & 1) << 3) + rr;
            int nc = bcol + g * 16 + ((m >> 1) << 3);
            ldsm4t(t, sptr(sBh + kr * SB + nc));
            bh[2*g][0]=t[0]; bh[2*g][1]=t[1]; bh[2*g+1][0]=t[2]; bh[2*g+1][1]=t[3];
            ldsm4t(t, sptr(sBl + kr * SB + nc));
            bl[2*g][0]=t[0]; bl[2*g][1]=t[1]; bl[2*g+1][0]=t[2]; bl[2*g+1][1]=t[3];
        }
    }
#pragma unroll
    for (int mi = 0; mi < 2; mi++)
#pragma unroll
        for (int ni = 0; ni < 4; ni++) {
            mma_bf(acc[mi][ni], ah[mi], bh[ni]);
            mma_bf(acc[mi][ni], ah[mi], bl[ni]);
            mma_bf(acc[mi][ni], al[mi], bh[ni]);
        }
}

// stage rows x (c8*8) split pair into smem with given stride (256 threads)
__device__ __forceinline__ void stage2(bf16* dh, bf16* dl, int stride,
    const bf16* gh, const bf16* gl, int ld, int rows, int c8, int tid)
{
    for (int i = tid; i < rows * c8; i += 256) {
        int r = i / c8, c = (i - r * c8) * 8;
        *(uint4*)(dh + r * stride + c) = *(const uint4*)(gh + (size_t)r * ld + c);
        *(uint4*)(dl + r * stride + c) = *(const uint4*)(gl + (size_t)r * ld + c);
    }
}

// ---------------- elementwise split ----------------
__global__ __launch_bounds__(256)
void split_kernel(const float* __restrict__ in, bf16* __restrict__ hi,
                  bf16* __restrict__ lo, int n) {
    int i = blockIdx.x * 256 + threadIdx.x;
    if (i < n) {
        float v = in[i];
        bf16 h = __float2bfloat16(v);
        hi[i] = h;
        lo[i] = __float2bfloat16(v - __bfloat162float(h));
    }
}

// ---------------- dense C = A @ B^T, block tile 128x64 ----------------
__global__ __launch_bounds__(256)
void tc_dense(const bf16* __restrict__ Ah, const bf16* __restrict__ Al, int lda,
              const bf16* __restrict__ Bh, const bf16* __restrict__ Bl, int ldb,
              int K, bf16* __restrict__ Ch, bf16* __restrict__ Cl,
              float* __restrict__ Cf, int ldc)
{
    __shared__ __align__(16) bf16 sAh[128*40], sAl[128*40], sBh[64*40], sBl[64*40];
    int tid = threadIdx.x, lane = tid & 31, w = tid >> 5;
    int m0 = blockIdx.y * 128, n0 = blockIdx.x * 64;
    int arow = (w >> 1) * 32, bcol = (w & 1) * 32;
    float acc[2][4][4] = {};
    for (int k0 = 0; k0 < K; k0 += 32) {
        stage2(sAh, sAl, 40, Ah + (size_t)m0*lda + k0, Al + (size_t)m0*lda + k0, lda, 128, 4, tid);
        stage2(sBh, sBl, 40, Bh + (size_t)n0*ldb + k0, Bl + (size_t)n0*ldb + k0, ldb, 64, 4, tid);
        __syncthreads();
        mma_tile<false>(acc, sAh, sAl, 40, arow, 0,  sBh, sBl, 40, bcol, 0,  lane);
        mma_tile<false>(acc, sAh, sAl, 40, arow, 16, sBh, sBl, 40, bcol, 16, lane);
        __syncthreads();
    }
    int r0 = arow + (lane >> 2), c0 = bcol + (lane & 3) * 2;
#pragma unroll
    for (int mi = 0; mi < 2; mi++)
#pragma unroll
        for (int ni = 0; ni < 4; ni++)
#pragma unroll
            for (int hf = 0; hf < 2; hf++) {
                int row = m0 + r0 + mi * 16 + hf * 8;
                int col = n0 + c0 + ni * 8;
                float v0 = acc[mi][ni][hf*2], v1 = acc[mi][ni][hf*2+1];
                size_t off = (size_t)row * ldc + col;
                if (Cf) *(float2*)&Cf[off] = make_float2(v0, v1);
                else    st_split2(Ch, Cl, off, v0, v1);
            }
}

// ---------------- per-head C = A @ B^T with causal mask, K=64, tile 128x64 ----------------
__global__ __launch_bounds__(256)
void tc_head(const bf16* __restrict__ Abh, const bf16* __restrict__ Abl,
             int a_hdiv, size_t a_per, int lda,
             const bf16* __restrict__ Bbh, const bf16* __restrict__ Bbl,
             int b_hdiv, size_t b_per, int ldb,
             const float* __restrict__ rowscale, int mode,
             bf16* __restrict__ Ch, bf16* __restrict__ Cl, float* __restrict__ Cf)
{
    int jt = blockIdx.x, it = blockIdx.y, h = blockIdx.z;
    if (jt > 2 * it + 1) return;
    __shared__ __align__(16) bf16 sAh[128*40], sAl[128*40], sBh[64*40], sBl[64*40];
    int tid = threadIdx.x, lane = tid & 31, w = tid >> 5;
    int arow = (w >> 1) * 32, bcol = (w & 1) * 32;
    const bf16* Ahp = Abh + (size_t)(a_hdiv ? (h >> 1) : h) * a_per + (size_t)(it*128) * lda;
    const bf16* Alp = Abl + (size_t)(a_hdiv ? (h >> 1) : h) * a_per + (size_t)(it*128) * lda;
    const bf16* Bhp = Bbh + (size_t)(b_hdiv ? (h >> 1) : h) * b_per + (size_t)(jt*64) * ldb;
    const bf16* Blp = Bbl + (size_t)(b_hdiv ? (h >> 1) : h) * b_per + (size_t)(jt*64) * ldb;
    float acc[2][4][4] = {};
#pragma unroll
    for (int k0 = 0; k0 < 64; k0 += 32) {
        stage2(sAh, sAl, 40, Ahp + k0, Alp + k0, lda, 128, 4, tid);
        stage2(sBh, sBl, 40, Bhp + k0, Blp + k0, ldb, 64, 4, tid);
        __syncthreads();
        mma_tile<false>(acc, sAh, sAl, 40, arow, 0,  sBh, sBl, 40, bcol, 0,  lane);
        mma_tile<false>(acc, sAh, sAl, 40, arow, 16, sBh, sBl, 40, bcol, 16, lane);
        __syncthreads();
    }
    int r0 = arow + (lane >> 2), c0 = bcol + (lane & 3) * 2;
    size_t hb = (size_t)h * HS;
#pragma unroll
    for (int mi = 0; mi < 2; mi++)
#pragma unroll
        for (int ni = 0; ni < 4; ni++)
#pragma unroll
            for (int hf = 0; hf < 2; hf++) {
                int row = it*128 + r0 + mi * 16 + hf * 8;
                int col = jt*64 + c0 + ni * 8;
                float v0 = acc[mi][ni][hf*2], v1 = acc[mi][ni][hf*2+1];
                float sc = rowscale ? rowscale[h * TT + row] : 1.f;
                v0 *= sc; v1 *= sc;
                if (mode == 1) { if (col   >= row) v0 = 0.f;
                                 if (col+1 >= row) v1 = 0.f; }
                else           { if (col   >  row) v0 = 0.f;
                                 if (col+1 >  row) v1 = 0.f; }
                size_t off = hb + (size_t)row * TT + col;
                if (Cf) *(float2*)&Cf[off] = make_float2(v0, v1);
                else    st_split2(Ch, Cl, off, v0, v1);
            }
}

// ---------------- invert (I + L) per 64x64 diagonal block ----------------
__global__ __launch_bounds__(64)
void compute_tinv() {
    __shared__ float L[64][65];
    __shared__ float X[64][65];
    int ch = blockIdx.x, h = blockIdx.y, c = threadIdx.x;
    size_t base = (size_t)h * HS + (size_t)(ch*64) * TT + ch*64;
    for (int r = 0; r < 64; r++) {
        L[r][c] = __bfloat162float(g_Mwh[base + (size_t)r*TT + c]) +
                  __bfloat162float(g_Mwl[base + (size_t)r*TT + c]);
        X[r][c] = (r == c) ? 1.f : 0.f;
    }
    __syncthreads();
    for (int r = 1; r < 64; r++) {
        if (c < r) {
            float acc = 0.f;
            for (int s = c; s < r; s++) acc += L[r][s] * X[s][c];
            X[r][c] = -acc;
        }
        __syncthreads();
    }
    size_t ob = ((size_t)(h*16 + ch)) * 4096;
    for (int r = 0; r < 64; r++) {
        float v = X[r][c];
        bf16 hh = __float2bfloat16(v);
        g_Tvh[ob + r*64 + c] = hh;
        g_Tvl[ob + r*64 + c] = __float2bfloat16(v - __bfloat162float(hh));
    }
}

// ---------------- blocked forward substitution, chunk ci; tile 64x128 ----------------
__global__ __launch_bounds__(256)
void tc_solve(int ci) {
    __shared__ __align__(16) char raw[45056];
    bf16* sMh = (bf16*)(raw);              // 64*40
    bf16* sMl = (bf16*)(raw + 5120);
    bf16* sKh = (bf16*)(raw + 10240);      // 32*136 (B chunk, T-form)
    bf16* sKl = (bf16*)(raw + 18944);
    bf16* sPh = (bf16*)(raw);              // 64*136 (phase 2)
    bf16* sPl = (bf16*)(raw + 17408);
    bf16* sTh = (bf16*)(raw + 34816);      // 64*40
    bf16* sTl = (bf16*)(raw + 39936);

    int jb = blockIdx.x, h = blockIdx.y;
    int tid = threadIdx.x, lane = tid & 31, w = tid >> 5;
    int arow = (w >> 2) * 32, bcol = (w & 3) * 32;
    size_t hb = (size_t)h * HS;
    int r0 = arow + (lane >> 2), c0 = bcol + (lane & 3) * 2;

    float acc[2][4][4];
#pragma unroll
    for (int mi = 0; mi < 2; mi++)
#pragma unroll
        for (int ni = 0; ni < 4; ni++)
#pragma unroll
            for (int hf = 0; hf < 2; hf++) {
                float2 v = *(const float2*)&g_rhs[hb +
                    (size_t)(ci*64 + r0 + mi*16 + hf*8) * TT + jb*128 + c0 + ni*8];
                acc[mi][ni][hf*2]   = -v.x;
                acc[mi][ni][hf*2+1] = -v.y;
            }

    for (int s = 2 * jb; s < ci; s++) {
#pragma unroll
        for (int kc = 0; kc < 64; kc += 32) {
            stage2(sMh, sMl, 40,
                   g_Mwh + hb + (size_t)(ci*64) * TT + s*64 + kc,
                   g_Mwl + hb + (size_t)(ci*64) * TT + s*64 + kc, TT, 64, 4, tid);
            stage2(sKh, sKl, 136,
                   g_Bh + hb + (size_t)(s*64 + kc) * TT + jb*128,
                   g_Bl + hb + (size_t)(s*64 + kc) * TT + jb*128, TT, 32, 16, tid);
            __syncthreads();
            mma_tile<true>(acc, sMh, sMl, 40, arow, 0,  sKh, sKl, 136, bcol, 0,  lane);
            mma_tile<true>(acc, sMh, sMl, 40, arow, 16, sKh, sKl, 136, bcol, 16, lane);
            __syncthreads();
        }
    }

    // P = -(acc) into smem split
#pragma unroll
    for (int mi = 0; mi < 2; mi++)
#pragma unroll
        for (int ni = 0; ni < 4; ni++)
#pragma unroll
            for (int hf = 0; hf < 2; hf++) {
                int r = r0 + mi*16 + hf*8, c = c0 + ni*8;
                st_split2(sPh, sPl, (size_t)r*136 + c,
                          -acc[mi][ni][hf*2], -acc[mi][ni][hf*2+1]);
            }

    // out = Tinv @ P
#pragma unroll
    for (int mi = 0; mi < 2; mi++)
#pragma unroll
        for (int ni = 0; ni < 4; ni++)
#pragma unroll
            for (int e = 0; e < 4; e++) acc[mi][ni][e] = 0.f;

    size_t tb = ((size_t)(h*16 + ci)) * 4096;
#pragma unroll
    for (int kc = 0; kc < 64; kc += 32) {
        stage2(sTh, sTl, 40, g_Tvh + tb + kc, g_Tvl + tb + kc, 64, 64, 4, tid);
        __syncthreads();
        mma_tile<true>(acc, sTh, sTl, 40, arow, 0,  sPh, sPl, 136, bcol, kc,      lane);
        mma_tile<true>(acc, sTh, sTl, 40, arow, 16, sPh, sPl, 136, bcol, kc + 16, lane);
        __syncthreads();
    }
#pragma unroll
    for (int mi = 0; mi < 2; mi++)
#pragma unroll
        for (int ni = 0; ni < 4; ni++)
#pragma unroll
            for (int hf = 0; hf < 2; hf++) {
                int row = ci*64 + r0 + mi*16 + hf*8;
                int col = jb*128 + c0 + ni*8;
                st_split2(g_Bh, g_Bl, hb + (size_t)row*TT + col,
                          acc[mi][ni][hf*2], acc[mi][ni][hf*2+1]);
            }
}

// ---------------- logits = (qk - QW @ Bmat) * scale, tile 128x64 ----------------
__global__ __launch_bounds__(256)
void tc_logits() {
    int jt = blockIdx.x, it = blockIdx.y, h = blockIdx.z;
    if (jt > 2 * it + 1) return;
    __shared__ __align__(16) bf16 sAh[128*40], sAl[128*40], sBh[32*72], sBl[32*72];
    int tid = threadIdx.x, lane = tid & 31, w = tid >> 5;
    int arow = (w >> 1) * 32, bcol = (w & 1) * 32;
    size_t hb = (size_t)h * HS;
    float acc[2][4][4] = {};
    int kb_hi = 2 * it + 1;
    for (int kb = jt; kb <= kb_hi; kb++) {
#pragma unroll
        for (int kc = 0; kc < 64; kc += 32) {
            stage2(sAh, sAl, 40,
                   g_QWh + hb + (size_t)(it*128) * TT + kb*64 + kc,
                   g_QWl + hb + (size_t)(it*128) * TT + kb*64 + kc, TT, 128, 4, tid);
            stage2(sBh, sBl, 72,
                   g_Bh + hb + (size_t)(kb*64 + kc) * TT + jt*64,
                   g_Bl + hb + (size_t)(kb*64 + kc) * TT + jt*64, TT, 32, 8, tid);
            __syncthreads();
            mma_tile<true>(acc, sAh, sAl, 40, arow, 0,  sBh, sBl, 72, bcol, 0,  lane);
            mma_tile<true>(acc, sAh, sAl, 40, arow, 16, sBh, sBl, 72, bcol, 16, lane);
            __syncthreads();
        }
    }
    int r0 = arow + (lane >> 2), c0 = bcol + (lane & 3) * 2;
#pragma unroll
    for (int mi = 0; mi < 2; mi++)
#pragma unroll
        for (int ni = 0; ni < 4; ni++)
#pragma unroll
            for (int hf = 0; hf < 2; hf++) {
                int row = it*128 + r0 + mi*16 + hf*8;
                int col = jt*64 + c0 + ni*8;
                size_t off = hb + (size_t)row*TT + col;
                float2 q = *(const float2*)&g_QK[off];
                *(float2*)&g_QK[off] = make_float2(
                    (q.x - acc[mi][ni][hf*2])   * ATT_SCALE,
                    (q.y - acc[mi][ni][hf*2+1]) * ATT_SCALE);
            }
}

// ---------------- causal row softmax -> split P (zeros above diag) ----------------
__global__ __launch_bounds__(128)
void softmax_rows() {
    int i = blockIdx.x, h = blockIdx.y, tid = threadIdx.x;
    float* row = g_QK + (size_t)h * HS + (size_t)i * TT;
    bf16* ph = g_Ph + (size_t)h * HS + (size_t)i * TT;
    bf16* pl = g_Pl + (size_t)h * HS + (size_t)i * TT;
    int n = i + 1;
    __shared__ float sh[4];
    float mx = -1e30f;
    for (int j = tid; j < n; j += 128) mx = fmaxf(mx, row[j]);
#pragma unroll
    for (int o = 16; o; o >>= 1) mx = fmaxf(mx, __shfl_xor_sync(~0u, mx, o));
    if ((tid & 31) == 0) sh[tid >> 5] = mx;
    __syncthreads();
    mx = fmaxf(fmaxf(sh[0], sh[1]), fmaxf(sh[2], sh[3]));
    __syncthreads();
    float sum = 0.f;
    for (int j = tid; j < n; j += 128) { float e = __expf(row[j] - mx); row[j] = e; sum += e; }
#pragma unroll
    for (int o = 16; o; o >>= 1) sum += __shfl_xor_sync(~0u, sum, o);
    if ((tid & 31) == 0) sh[tid >> 5] = sum;
    __syncthreads();
    sum = sh[0] + sh[1] + sh[2] + sh[3];
    float inv = 1.f / sum;
    for (int j = tid; j < TT; j += 128) {
        float p = (j < n) ? row[j] * inv : 0.f;
        bf16 hh = __float2bfloat16(p);
        ph[j] = hh;
        pl[j] = __float2bfloat16(p - __bfloat162float(hh));
    }
}

// ---------------- O2 = P @ V per head, tile 128x64 ----------------
__global__ __launch_bounds__(256)
void tc_pv() {
    int it = blockIdx.x, h = blockIdx.y;
    __shared__ __align__(16) bf16 sAh[128*40], sAl[128*40], sBh[32*72], sBl[32*72];
    int tid = threadIdx.x, lane = tid & 31, w = tid >> 5;
    int arow = (w >> 1) * 32, bcol = (w & 1) * 32;
    size_t hb = (size_t)h * HS;
    const bf16* vh = g_vh + (size_t)(h >> 1) * 64;
    const bf16* vl = g_vl + (size_t)(h >> 1) * 64;
    float acc[2][4][4] = {};
    int kb_hi = 2 * it + 1;
    for (int kb = 0; kb <= kb_hi; kb++) {
#pragma unroll
        for (int kc = 0; kc < 64; kc += 32) {
            stage2(sAh, sAl, 40,
                   g_Ph + hb + (size_t)(it*128) * TT + kb*64 + kc,
                   g_Pl + hb + (size_t)(it*128) * TT + kb*64 + kc, TT, 128, 4, tid);
            stage2(sBh, sBl, 72,
                   vh + (size_t)(kb*64 + kc) * 1024,
                   vl + (size_t)(kb*64 + kc) * 1024, 1024, 32, 8, tid);
            __syncthreads();
            mma_tile<true>(acc, sAh, sAl, 40, arow, 0,  sBh, sBl, 72, bcol, 0,  lane);
            mma_tile<true>(acc, sAh, sAl, 40, arow, 16, sBh, sBl, 72, bcol, 16, lane);
            __syncthreads();
        }
    }
    int r0 = arow + (lane >> 2), c0 = bcol + (lane & 3) * 2;
#pragma unroll
    for (int mi = 0; mi < 2; mi++)
#pragma unroll
        for (int ni = 0; ni < 4; ni++)
#pragma unroll
            for (int hf = 0; hf < 2; hf++) {
                int row = it*128 + r0 + mi*16 + hf*8;
                int col = c0 + ni*8;
                st_split2(g_O2h, g_O2l, (size_t)row * 2048 + h*64 + col,
                          acc[mi][ni][hf*2], acc[mi][ni][hf*2+1]);
            }
}

// ---------------- small fp32 GEMM (low-rank / beta paths) ----------------
__global__ __launch_bounds__(256)
void gemm_abt(const float* __restrict__ A, const float* __restrict__ B,
              float* __restrict__ C, int M, int N, int K,
              int lda, int ldb, int ldc) {
    __shared__ float As[16][64], Bs[16][64];
    int n0 = blockIdx.x * 64, m0 = blockIdx.y * 64;
    int tid = threadIdx.x;
    int r  = tid >> 2;
    int kq = (tid & 3) * 4;
    int tr4 = (tid >> 4) * 4, tc4 = (tid & 15) * 4;
    float acc[4][4] = {};
    for (int k0 = 0; k0 < K; k0 += 16) {
        float4 a4 = *(const float4*)(A + (size_t)(m0 + r) * lda + k0 + kq);
        As[kq+0][r]=a4.x; As[kq+1][r]=a4.y; As[kq+2][r]=a4.z; As[kq+3][r]=a4.w;
        if (n0 + r < N) {
            float4 b4 = *(const float4*)(B + (size_t)(n0 + r) * ldb + k0 + kq);
            Bs[kq+0][r]=b4.x; Bs[kq+1][r]=b4.y; Bs[kq+2][r]=b4.z; Bs[kq+3][r]=b4.w;
        } else {
            Bs[kq+0][r]=0.f; Bs[kq+1][r]=0.f; Bs[kq+2][r]=0.f; Bs[kq+3][r]=0.f;
        }
        __syncthreads();
#pragma unroll
        for (int kk = 0; kk < 16; kk++) {
            float4 a = *(const float4*)&As[kk][tr4];
            float4 b = *(const float4*)&Bs[kk][tc4];
            float av[4]={a.x,a.y,a.z,a.w}, bv[4]={b.x,b.y,b.z,b.w};
#pragma unroll
            for (int i=0;i<4;i++)
#pragma unroll
                for (int j=0;j<4;j++) acc[i][j] += av[i]*bv[j];
        }
        __syncthreads();
    }
#pragma unroll
    for (int i = 0; i < 4; i++)
#pragma unroll
        for (int j = 0; j < 4; j++) {
            int col = n0 + tc4 + j;
            if (col < N) C[(size_t)(m0 + tr4 + i) * ldc + col] = acc[i][j];
        }
}

__global__ void beta_fix(const float* __restrict__ tmp, const float* __restrict__ bias,
                         float* __restrict__ betah) {
    int idx = blockIdx.x * blockDim.x + threadIdx.x;
    int t = idx >> 5, hr = idx & 31;
    betah[hr*TT + t] = 2.f / (1.f + __expf(-(tmp[t*32 + hr] + bias[hr])));
}

__global__ __launch_bounds__(64)
void wdir_kernel(const float* __restrict__ wraw, const float* __restrict__ conv_w,
                 const float* __restrict__ omega, const float* __restrict__ phi) {
    int t = blockIdx.x, hr = blockIdx.y, d = threadIdx.x;
    int hkv = hr >> 1, r = hr & 1;
    int cA = hkv * 256 + (2*r) * 64 + d;
    int cB = cA + 64;
    float a = 0.f, b = 0.f;
#pragma unroll
    for (int i = 0; i < 3; i++) {
        int tt = t + i - 2;
        if (tt >= 0) {
            a += wraw[(size_t)tt * 4096 + cA] * conv_w[cA*3 + i];
            b += wraw[(size_t)tt * 4096 + cB] * conv_w[cB*3 + i];
        }
    }
    a = a / (1.f + expf(-a));
    b = b / (1.f + expf(-b));
    float th = omega[r] * (float)t + phi[r];
    float w = a * cosf(th) + b * sinf(th);
    float ss = w * w;
#pragma unroll
    for (int o = 16; o; o >>= 1) ss += __shfl_xor_sync(~0u, ss, o);
    __shared__ float sh[2];
    if ((d & 31) == 0) sh[d >> 5] = ss;
    __syncthreads();
    float tot = sh[0] + sh[1];
    float val = w * rsqrtf(tot + 1e-6f);
    size_t off = ((size_t)hr * TT + t) * 64 + d;
    bf16 hh = __float2bfloat16(val);
    g_wdh[off] = hh;
    g_wdl[off] = __float2bfloat16(val - __bfloat162float(hh));
}

// ---------------- driver ----------------
extern "C" void kernel_launch(void* const* d_in, const int* in_sizes, int n_in,
                              void* d_out, int out_size) {
    const float* x    = (const float*)d_in[0];
    const float* q_w  = (const float*)d_in[1];
    const float* k_w  = (const float*)d_in[2];
    const float* v_w  = (const float*)d_in[3];
    const float* w1   = (const float*)d_in[4];
    const float* w2   = (const float*)d_in[5];
    const float* cw   = (const float*)d_in[6];
    const float* btw  = (const float*)d_in[7];
    const float* btb  = (const float*)d_in[8];
    const float* ow   = (const float*)d_in[9];
    const float* omega= (const float*)d_in[10];
    const float* phi  = (const float*)d_in[11];
    float* out = (float*)d_out;

    float *pwlow,*pwraw,*pbtmp,*pbetah,*pQK,*prhs;
    bf16 *pxh,*pxl,*pqwh,*pqwl,*pkwh,*pkwl,*pvwh,*pvwl,*powh,*powl;
    bf16 *pqh,*pql,*pkh,*pkl,*pvh,*pvl,*pwdh,*pwdl;
    bf16 *pMwh,*pMwl,*pQWh,*pQWl,*pO2h,*pO2l;
    cudaGetSymbolAddress((void**)&pwlow, g_wlow);
    cudaGetSymbolAddress((void**)&pwraw, g_wraw);
    cudaGetSymbolAddress((void**)&pbtmp, g_btmp);
    cudaGetSymbolAddress((void**)&pbetah,g_betah);
    cudaGetSymbolAddress((void**)&pQK,   g_QK);
    cudaGetSymbolAddress((void**)&prhs,  g_rhs);
    cudaGetSymbolAddress((void**)&pxh,  g_xh);  cudaGetSymbolAddress((void**)&pxl,  g_xl);
    cudaGetSymbolAddress((void**)&pqwh, g_qwh); cudaGetSymbolAddress((void**)&pqwl, g_qwl);
    cudaGetSymbolAddress((void**)&pkwh, g_kwh); cudaGetSymbolAddress((void**)&pkwl, g_kwl);
    cudaGetSymbolAddress((void**)&pvwh, g_vwh); cudaGetSymbolAddress((void**)&pvwl, g_vwl);
    cudaGetSymbolAddress((void**)&powh, g_owh); cudaGetSymbolAddress((void**)&powl, g_owl);
    cudaGetSymbolAddress((void**)&pqh,  g_qh);  cudaGetSymbolAddress((void**)&pql,  g_ql);
    cudaGetSymbolAddress((void**)&pkh,  g_kh);  cudaGetSymbolAddress((void**)&pkl,  g_kl);
    cudaGetSymbolAddress((void**)&pvh,  g_vh);  cudaGetSymbolAddress((void**)&pvl,  g_vl);
    cudaGetSymbolAddress((void**)&pwdh, g_wdh); cudaGetSymbolAddress((void**)&pwdl, g_wdl);
    cudaGetSymbolAddress((void**)&pMwh, g_Mwh); cudaGetSymbolAddress((void**)&pMwl, g_Mwl);
    cudaGetSymbolAddress((void**)&pQWh, g_QWh); cudaGetSymbolAddress((void**)&pQWl, g_QWl);
    cudaGetSymbolAddress((void**)&pO2h, g_O2h); cudaGetSymbolAddress((void**)&pO2l, g_O2l);

    // splits
    split_kernel<<<4096, 256>>>(x,   pxh,  pxl,  1048576);
    split_kernel<<<4096, 256>>>(q_w, pqwh, pqwl, 1048576);
    split_kernel<<<4096, 256>>>(k_w, pkwh, pkwl, 1048576);
    split_kernel<<<4096, 256>>>(v_w, pvwh, pvwl, 1048576);
    split_kernel<<<8192, 256>>>(ow,  powh, powl, 2097152);

    // low-rank / beta paths (fp32)
    gemm_abt<<<dim3(1,16),  256>>>(x, w1, pwlow, 1024, 32, 1024, 1024, 1024, 32);
    gemm_abt<<<dim3(64,16), 256>>>(pwlow, w2, pwraw, 1024, 4096, 32, 32, 32, 4096);
    gemm_abt<<<dim3(1,16),  256>>>(x, btw, pbtmp, 1024, 32, 1024, 1024, 1024, 32);
    beta_fix<<<128, 256>>>(pbtmp, btb, pbetah);
    wdir_kernel<<<dim3(1024, 32), 64>>>(pwraw, cw, omega, phi);

    // projections (tensor core, split output)
    tc_dense<<<dim3(16,8), 256>>>(pxh, pxl, 1024, pqwh, pqwl, 1024, 1024, pqh, pql, nullptr, 1024);
    tc_dense<<<dim3(16,8), 256>>>(pxh, pxl, 1024, pkwh, pkwl, 1024, 1024, pkh, pkl, nullptr, 1024);
    tc_dense<<<dim3(16,8), 256>>>(pxh, pxl, 1024, pvwh, pvwl, 1024, 1024, pvh, pvl, nullptr, 1024);

    // per-head matrices
    tc_head<<<dim3(16,8,32), 256>>>(pwdh, pwdl, 0, 65536, 64, pwdh, pwdl, 0, 65536, 64,
                                    pbetah, 1, pMwh, pMwl, nullptr);              // Mw (split)
    tc_head<<<dim3(16,8,32), 256>>>(pwdh, pwdl, 0, 65536, 64, pkh, pkl, 1, 64, 1024,
                                    pbetah, 1, nullptr, nullptr, prhs);           // rhs (f32)
    tc_head<<<dim3(16,8,32), 256>>>(pqh, pql, 1, 64, 1024, pkh, pkl, 1, 64, 1024,
                                    nullptr, 2, nullptr, nullptr, pQK);           // QK (f32)
    tc_head<<<dim3(16,8,32), 256>>>(pqh, pql, 1, 64, 1024, pwdh, pwdl, 0, 65536, 64,
                                    nullptr, 2, pQWh, pQWl, nullptr);             // QW (split)

    // triangular solve
    compute_tinv<<<dim3(16,32), 64>>>();
    for (int ci = 0; ci < 16; ci++)
        tc_solve<<<dim3(ci/2 + 1, 32), 256>>>(ci);

    // attention
    tc_logits<<<dim3(16,8,32), 256>>>();
    softmax_rows<<<dim3(1024,32), 128>>>();
    tc_pv<<<dim3(8,32), 256>>>();

    // output projection
    tc_dense<<<dim3(16,8), 256>>>(pO2h, pO2l, 2048, powh, powl, 2048, 2048,
                                  nullptr, nullptr, out, 1024);
}

// round 6
// speedup vs baseline: 2.0069x; 1.3488x over previous
#include <cuda_runtime.h>
#include <cuda_bf16.h>
#include <cstdint>

using bf16 = __nv_bfloat16;
#define TT 1024
#define HS 1048576
#define ATT_SCALE 0.125f

__device__ float g_wlow[TT*32];
__device__ float g_wraw[TT*4096];
__device__ float g_btmp[TT*32];
__device__ float g_betah[32*TT];
__device__ float g_rhs[32*HS];
__device__ float g_QK [16*HS];

__device__ bf16 g_xh[1048576],  g_xl[1048576];
__device__ bf16 g_qwh[1048576], g_qwl[1048576];
__device__ bf16 g_kwh[1048576], g_kwl[1048576];
__device__ bf16 g_vwh[1048576], g_vwl[1048576];
__device__ bf16 g_owh[2097152], g_owl[2097152];
__device__ bf16 g_qh[1048576],  g_ql[1048576];
__device__ bf16 g_kh[1048576],  g_kl[1048576];
__device__ bf16 g_vh[1048576],  g_vl[1048576];
__device__ bf16 g_wdh[2097152], g_wdl[2097152];
__device__ bf16 g_Mwh[33554432], g_Mwl[33554432];
__device__ bf16 g_Bh [33554432], g_Bl [33554432];
__device__ bf16 g_QWh[33554432], g_QWl[33554432];
__device__ bf16 g_Ph [33554432], g_Pl [33554432];
__device__ bf16 g_Tvh[2097152],  g_Tvl[2097152];
__device__ bf16 g_O2h[2097152],  g_O2l[2097152];

__device__ __forceinline__ uint32_t sptr(const void* p) {
    return (uint32_t)__cvta_generic_to_shared(p);
}
__device__ __forceinline__ void ldsm4(uint32_t* r, uint32_t a) {
    asm volatile("ldmatrix.sync.aligned.m8n8.x4.shared.b16 {%0,%1,%2,%3}, [%4];"
        : "=r"(r[0]), "=r"(r[1]), "=r"(r[2]), "=r"(r[3]) : "r"(a));
}
__device__ __forceinline__ void ldsm4t(uint32_t* r, uint32_t a) {
    asm volatile("ldmatrix.sync.aligned.m8n8.x4.trans.shared.b16 {%0,%1,%2,%3}, [%4];"
        : "=r"(r[0]), "=r"(r[1]), "=r"(r[2]), "=r"(r[3]) : "r"(a));
}
__device__ __forceinline__ void mma_bf(float* c, const uint32_t* a, const uint32_t* b) {
    asm volatile(
        "mma.sync.aligned.m16n8k16.row.col.f32.bf16.bf16.f32 "
        "{%0,%1,%2,%3},{%4,%5,%6,%7},{%8,%9},{%0,%1,%2,%3};"
        : "+f"(c[0]), "+f"(c[1]), "+f"(c[2]), "+f"(c[3])
        : "r"(a[0]), "r"(a[1]), "r"(a[2]), "r"(a[3]), "r"(b[0]), "r"(b[1]));
}
__device__ __forceinline__ void st_split2(bf16* hi, bf16* lo, size_t off, float v0, float v1) {
    bf16 h0 = __float2bfloat16(v0), h1 = __float2bfloat16(v1);
    *(__nv_bfloat162*)(hi + off) = __halves2bfloat162(h0, h1);
    *(__nv_bfloat162*)(lo + off) = __halves2bfloat162(
        __float2bfloat16(v0 - __bfloat162float(h0)),
        __float2bfloat16(v1 - __bfloat162float(h1)));
}
__device__ __forceinline__ void cpa16(void* s, const void* g) {
    asm volatile("cp.async.cg.shared.global [%0], [%1], 16;" :: "r"(sptr(s)), "l"(g) : "memory");
}
#define CPC() asm volatile("cp.async.commit_group;" ::: "memory")
#define CPW(n) asm volatile("cp.async.wait_group %0;" :: "n"(n) : "memory")

template<bool TRANSB>
__device__ __forceinline__ void mma_tile(float (&acc)[2][4][4],
    const bf16* sAh, const bf16* sAl, int SA, int arow, int ka0,
    const bf16* sBh, const bf16* sBl, int SB, int bcol, int kb0, int lane)
{
    uint32_t ah[2][4], al[2][4];
    {
        int r = arow + (lane & 15);
        int c = ka0 + ((lane >> 4) << 3);
        ldsm4(ah[0], sptr(sAh + r * SA + c));
        ldsm4(ah[1], sptr(sAh + (r + 16) * SA + c));
        ldsm4(al[0], sptr(sAl + r * SA + c));
        ldsm4(al[1], sptr(sAl + (r + 16) * SA + c));
    }
    uint32_t bh[4][2], bl[4][2];
    int m = lane >> 3, rr = lane & 7;
#pragma unroll
    for (int g = 0; g < 2; g++) {
        uint32_t t[4];
        if (!TRANSB) {
            int n  = bcol + g * 16 + ((m >> 1) << 3) + rr;
            int kk = kb0 + ((m & 1) << 3);
            ldsm4(t, sptr(sBh + n * SB + kk));
            bh[2*g][0]=t[0]; bh[2*g][1]=t[1]; bh[2*g+1][0]=t[2]; bh[2*g+1][1]=t[3];
            ldsm4(t, sptr(sBl + n * SB + kk));
            bl[2*g][0]=t[0]; bl[2*g][1]=t[1]; bl[2*g+1][0]=t[2]; bl[2*g+1][1]=t[3];
        } else {
            int kr = kb0 + ((m & 1) << 3) + rr;
            int nc = bcol + g * 16 + ((m >> 1) << 3);
            ldsm4t(t, sptr(sBh + kr * SB + nc));
            bh[2*g][0]=t[0]; bh[2*g][1]=t[1]; bh[2*g+1][0]=t[2]; bh[2*g+1][1]=t[3];
            ldsm4t(t, sptr(sBl + kr * SB + nc));
            bl[2*g][0]=t[0]; bl[2*g][1]=t[1]; bl[2*g+1][0]=t[2]; bl[2*g+1][1]=t[3];
        }
    }
#pragma unroll
    for (int mi = 0; mi < 2; mi++)
#pragma unroll
        for (int ni = 0; ni < 4; ni++) {
            mma_bf(acc[mi][ni], ah[mi], bh[ni]);
            mma_bf(acc[mi][ni], ah[mi], bl[ni]);
            mma_bf(acc[mi][ni], al[mi], bh[ni]);
        }
}

// async stage rows x (c8*8) split pair -> smem, 256 threads
__device__ __forceinline__ void stage2a(bf16* dh, bf16* dl, int stride,
    const bf16* gh, const bf16* gl, int ld, int rows, int c8, int tid)
{
    for (int i = tid; i < rows * c8; i += 256) {
        int r = i / c8, c = (i - r * c8) * 8;
        cpa16(dh + r * stride + c, gh + (size_t)r * ld + c);
        cpa16(dl + r * stride + c, gl + (size_t)r * ld + c);
    }
}

__global__ __launch_bounds__(256)
void split_kernel(const float* __restrict__ in, bf16* __restrict__ hi,
                  bf16* __restrict__ lo, int n) {
    int i = blockIdx.x * 256 + threadIdx.x;
    if (i < n) {
        float v = in[i];
        bf16 h = __float2bfloat16(v);
        hi[i] = h;
        lo[i] = __float2bfloat16(v - __bfloat162float(h));
    }
}

// ---- fused x@w1^T (32) and x@btw^T (32) per token ----
__global__ __launch_bounds__(256)
void lowrank(const float* __restrict__ x, const float* __restrict__ w1,
             const float* __restrict__ btw, float* __restrict__ wlow, float* __restrict__ btmp) {
    __shared__ float sx[1024];
    __shared__ float red[64][5];
    int t = blockIdx.x, tid = threadIdx.x;
    *(float4*)&sx[tid*4] = *(const float4*)&x[(size_t)t*1024 + tid*4];
    __syncthreads();
    int c = tid & 63, s = tid >> 6;
    const float* w = (c < 32) ? (w1 + (size_t)c*1024) : (btw + (size_t)(c-32)*1024);
    float acc = 0.f;
    for (int k = s*256; k < s*256 + 256; k += 4) {
        float4 wv = *(const float4*)&w[k];
        acc += wv.x*sx[k] + wv.y*sx[k+1] + wv.z*sx[k+2] + wv.w*sx[k+3];
    }
    red[c][s] = acc;
    __syncthreads();
    if (tid < 64) {
        float v = red[tid][0] + red[tid][1] + red[tid][2] + red[tid][3];
        if (tid < 32) wlow[t*32 + tid] = v;
        else          btmp[t*32 + tid - 32] = v;
    }
}

// ---- dense C = A@B^T, tile 128x64, pipelined ----
__global__ __launch_bounds__(256)
void tc_dense(const bf16* __restrict__ Ah, const bf16* __restrict__ Al, int lda,
              const bf16* __restrict__ Bh, const bf16* __restrict__ Bl, int ldb,
              int K, bf16* __restrict__ Ch, bf16* __restrict__ Cl,
              float* __restrict__ Cf, int ldc)
{
    extern __shared__ __align__(16) bf16 sm[];
    const int BUF = 15360;
    int tid = threadIdx.x, lane = tid & 31, w = tid >> 5;
    int m0 = blockIdx.y * 128, n0 = blockIdx.x * 64;
    int arow = (w >> 1) * 32, bcol = (w & 1) * 32;
    float acc[2][4][4] = {};
    int nk = K / 32;
    auto stg = [&](int b, int k0) {
        bf16* p = sm + b * BUF;
        stage2a(p, p+5120, 40, Ah + (size_t)m0*lda + k0, Al + (size_t)m0*lda + k0, lda, 128, 4, tid);
        stage2a(p+10240, p+12800, 40, Bh + (size_t)n0*ldb + k0, Bl + (size_t)n0*ldb + k0, ldb, 64, 4, tid);
        CPC();
    };
    stg(0, 0);
    for (int i = 0; i < nk; i++) {
        if (i+1 < nk) { stg((i+1)&1, (i+1)*32); CPW(1); } else CPW(0);
        __syncthreads();
        bf16* p = sm + (i&1)*BUF;
        mma_tile<false>(acc, p, p+5120, 40, arow, 0,  p+10240, p+12800, 40, bcol, 0,  lane);
        mma_tile<false>(acc, p, p+5120, 40, arow, 16, p+10240, p+12800, 40, bcol, 16, lane);
        __syncthreads();
    }
    int r0 = arow + (lane >> 2), c0 = bcol + (lane & 3) * 2;
#pragma unroll
    for (int mi = 0; mi < 2; mi++)
#pragma unroll
        for (int ni = 0; ni < 4; ni++)
#pragma unroll
            for (int hf = 0; hf < 2; hf++) {
                int row = m0 + r0 + mi*16 + hf*8;
                int col = n0 + c0 + ni*8;
                float v0 = acc[mi][ni][hf*2], v1 = acc[mi][ni][hf*2+1];
                size_t off = (size_t)row * ldc + col;
                if (Cf) *(float2*)&Cf[off] = make_float2(v0, v1);
                else    st_split2(Ch, Cl, off, v0, v1);
            }
}

// ---- per-head C = A@B^T, K=64, causal mask, pipelined ----
__global__ __launch_bounds__(256)
void tc_head(const bf16* __restrict__ Abh, const bf16* __restrict__ Abl,
             int a_hdiv, size_t a_per, int lda,
             const bf16* __restrict__ Bbh, const bf16* __restrict__ Bbl,
             int b_hdiv, size_t b_per, int ldb,
             const float* __restrict__ rowscale, int mode,
             bf16* __restrict__ Ch, bf16* __restrict__ Cl, float* __restrict__ Cf)
{
    int jt = blockIdx.x, it = blockIdx.y, h = blockIdx.z;
    if (jt > 2 * it + 1) return;
    extern __shared__ __align__(16) bf16 sm[];
    const int BUF = 15360;
    int tid = threadIdx.x, lane = tid & 31, w = tid >> 5;
    int arow = (w >> 1) * 32, bcol = (w & 1) * 32;
    const bf16* Ahp = Abh + (size_t)(a_hdiv ? (h >> 1) : h) * a_per + (size_t)(it*128) * lda;
    const bf16* Alp = Abl + (size_t)(a_hdiv ? (h >> 1) : h) * a_per + (size_t)(it*128) * lda;
    const bf16* Bhp = Bbh + (size_t)(b_hdiv ? (h >> 1) : h) * b_per + (size_t)(jt*64) * ldb;
    const bf16* Blp = Bbl + (size_t)(b_hdiv ? (h >> 1) : h) * b_per + (size_t)(jt*64) * ldb;
    float acc[2][4][4] = {};
    auto stg = [&](int b, int k0) {
        bf16* p = sm + b * BUF;
        stage2a(p, p+5120, 40, Ahp + k0, Alp + k0, lda, 128, 4, tid);
        stage2a(p+10240, p+12800, 40, Bhp + k0, Blp + k0, ldb, 64, 4, tid);
        CPC();
    };
    stg(0, 0);
#pragma unroll
    for (int i = 0; i < 2; i++) {
        if (i == 0) { stg(1, 32); CPW(1); } else CPW(0);
        __syncthreads();
        bf16* p = sm + i*BUF;
        mma_tile<false>(acc, p, p+5120, 40, arow, 0,  p+10240, p+12800, 40, bcol, 0,  lane);
        mma_tile<false>(acc, p, p+5120, 40, arow, 16, p+10240, p+12800, 40, bcol, 16, lane);
        __syncthreads();
    }
    int r0 = arow + (lane >> 2), c0 = bcol + (lane & 3) * 2;
    size_t hb = (size_t)h * HS;
#pragma unroll
    for (int mi = 0; mi < 2; mi++)
#pragma unroll
        for (int ni = 0; ni < 4; ni++)
#pragma unroll
            for (int hf = 0; hf < 2; hf++) {
                int row = it*128 + r0 + mi*16 + hf*8;
                int col = jt*64 + c0 + ni*8;
                float v0 = acc[mi][ni][hf*2], v1 = acc[mi][ni][hf*2+1];
                float sc = rowscale ? rowscale[h * TT + row] : 1.f;
                v0 *= sc; v1 *= sc;
                if (mode == 1) { if (col   >= row) v0 = 0.f;
                                 if (col+1 >= row) v1 = 0.f; }
                else           { if (col   >  row) v0 = 0.f;
                                 if (col+1 >  row) v1 = 0.f; }
                size_t off = hb + (size_t)row * TT + col;
                if (Cf) *(float2*)&Cf[off] = make_float2(v0, v1);
                else    st_split2(Ch, Cl, off, v0, v1);
            }
}

__global__ __launch_bounds__(64)
void compute_tinv() {
    __shared__ float L[64][65];
    __shared__ float X[64][65];
    int ch = blockIdx.x, h = blockIdx.y, c = threadIdx.x;
    size_t base = (size_t)h * HS + (size_t)(ch*64) * TT + ch*64;
    for (int r = 0; r < 64; r++) {
        L[r][c] = __bfloat162float(g_Mwh[base + (size_t)r*TT + c]) +
                  __bfloat162float(g_Mwl[base + (size_t)r*TT + c]);
        X[r][c] = (r == c) ? 1.f : 0.f;
    }
    __syncthreads();
    for (int r = 1; r < 64; r++) {
        if (c < r) {
            float acc = 0.f;
            for (int s = c; s < r; s++) acc += L[r][s] * X[s][c];
            X[r][c] = -acc;
        }
        __syncthreads();
    }
    size_t ob = ((size_t)(h*16 + ch)) * 4096;
    for (int r = 0; r < 64; r++) {
        float v = X[r][c];
        bf16 hh = __float2bfloat16(v);
        g_Tvh[ob + r*64 + c] = hh;
        g_Tvl[ob + r*64 + c] = __float2bfloat16(v - __bfloat162float(hh));
    }
}

// ---- blocked forward substitution, chunk ci; tile 64x128, pipelined ----
__global__ __launch_bounds__(256)
void tc_solve(int ci) {
    extern __shared__ __align__(16) bf16 sm[];
    const int BUF = 13824;  // Mh 2560 | Ml 2560 | Kh 4352 | Kl 4352
    int jb = blockIdx.x, h = blockIdx.y;
    int tid = threadIdx.x, lane = tid & 31, w = tid >> 5;
    int arow = (w >> 2) * 32, bcol = (w & 3) * 32;
    size_t hb = (size_t)h * HS;
    int r0 = arow + (lane >> 2), c0 = bcol + (lane & 3) * 2;
    float acc[2][4][4];
#pragma unroll
    for (int mi = 0; mi < 2; mi++)
#pragma unroll
        for (int ni = 0; ni < 4; ni++)
#pragma unroll
            for (int hf = 0; hf < 2; hf++) {
                float2 v = *(const float2*)&g_rhs[hb +
                    (size_t)(ci*64 + r0 + mi*16 + hf*8) * TT + jb*128 + c0 + ni*8];
                acc[mi][ni][hf*2]   = -v.x;
                acc[mi][ni][hf*2+1] = -v.y;
            }
    int nch = 2 * (ci - 2*jb);
    auto stg = [&](int b, int m) {
        int s = 2*jb + (m >> 1), kc = (m & 1) * 32;
        bf16* p = sm + b * BUF;
        stage2a(p, p+2560, 40,
                g_Mwh + hb + (size_t)(ci*64)*TT + s*64 + kc,
                g_Mwl + hb + (size_t)(ci*64)*TT + s*64 + kc, TT, 64, 4, tid);
        stage2a(p+5120, p+9472, 136,
                g_Bh + hb + (size_t)(s*64 + kc)*TT + jb*128,
                g_Bl + hb + (size_t)(s*64 + kc)*TT + jb*128, TT, 32, 16, tid);
        CPC();
    };
    if (nch > 0) stg(0, 0);
    for (int m = 0; m < nch; m++) {
        if (m+1 < nch) { stg((m+1)&1, m+1); CPW(1); } else CPW(0);
        __syncthreads();
        bf16* p = sm + (m&1)*BUF;
        mma_tile<true>(acc, p, p+2560, 40, arow, 0,  p+5120, p+9472, 136, bcol, 0,  lane);
        mma_tile<true>(acc, p, p+2560, 40, arow, 16, p+5120, p+9472, 136, bcol, 16, lane);
        __syncthreads();
    }
    // phase 2: P into smem split, then Tinv @ P
    bf16 *sPh = sm, *sPl = sm + 8704, *sTh = sm + 17408, *sTl = sm + 19968;
    __syncthreads();
#pragma unroll
    for (int mi = 0; mi < 2; mi++)
#pragma unroll
        for (int ni = 0; ni < 4; ni++)
#pragma unroll
            for (int hf = 0; hf < 2; hf++) {
                int r = r0 + mi*16 + hf*8, c = c0 + ni*8;
                st_split2(sPh, sPl, (size_t)r*136 + c,
                          -acc[mi][ni][hf*2], -acc[mi][ni][hf*2+1]);
            }
#pragma unroll
    for (int mi = 0; mi < 2; mi++)
#pragma unroll
        for (int ni = 0; ni < 4; ni++)
#pragma unroll
            for (int e = 0; e < 4; e++) acc[mi][ni][e] = 0.f;
    size_t tb = ((size_t)(h*16 + ci)) * 4096;
#pragma unroll
    for (int kc = 0; kc < 64; kc += 32) {
        stage2a(sTh, sTl, 40, g_Tvh + tb + kc, g_Tvl + tb + kc, 64, 64, 4, tid);
        CPC(); CPW(0);
        __syncthreads();
        mma_tile<true>(acc, sTh, sTl, 40, arow, 0,  sPh, sPl, 136, bcol, kc,      lane);
        mma_tile<true>(acc, sTh, sTl, 40, arow, 16, sPh, sPl, 136, bcol, kc + 16, lane);
        __syncthreads();
    }
#pragma unroll
    for (int mi = 0; mi < 2; mi++)
#pragma unroll
        for (int ni = 0; ni < 4; ni++)
#pragma unroll
            for (int hf = 0; hf < 2; hf++) {
                int row = ci*64 + r0 + mi*16 + hf*8;
                int col = jb*128 + c0 + ni*8;
                st_split2(g_Bh, g_Bl, hb + (size_t)row*TT + col,
                          acc[mi][ni][hf*2], acc[mi][ni][hf*2+1]);
            }
}

// ---- logits = (qk - QW@Bmat)*scale -> g_rhs, pipelined ----
__global__ __launch_bounds__(256)
void tc_logits() {
    int jt = blockIdx.x, it = blockIdx.y, h = blockIdx.z;
    if (jt > 2 * it + 1) return;
    extern __shared__ __align__(16) bf16 sm[];
    const int BUF = 14848;  // Ah 5120 | Al 5120 | Bh 2304 | Bl 2304
    int tid = threadIdx.x, lane = tid & 31, w = tid >> 5;
    int arow = (w >> 1) * 32, bcol = (w & 1) * 32;
    size_t hb = (size_t)h * HS;
    float acc[2][4][4] = {};
    int nch = 2 * (2*it + 2 - jt);
    auto stg = [&](int b, int m) {
        int kb = jt + (m >> 1), kc = (m & 1) * 32;
        bf16* p = sm + b * BUF;
        stage2a(p, p+5120, 40,
                g_QWh + hb + (size_t)(it*128)*TT + kb*64 + kc,
                g_QWl + hb + (size_t)(it*128)*TT + kb*64 + kc, TT, 128, 4, tid);
        stage2a(p+10240, p+12544, 72,
                g_Bh + hb + (size_t)(kb*64 + kc)*TT + jt*64,
                g_Bl + hb + (size_t)(kb*64 + kc)*TT + jt*64, TT, 32, 8, tid);
        CPC();
    };
    stg(0, 0);
    for (int m = 0; m < nch; m++) {
        if (m+1 < nch) { stg((m+1)&1, m+1); CPW(1); } else CPW(0);
        __syncthreads();
        bf16* p = sm + (m&1)*BUF;
        mma_tile<true>(acc, p, p+5120, 40, arow, 0,  p+10240, p+12544, 72, bcol, 0,  lane);
        mma_tile<true>(acc, p, p+5120, 40, arow, 16, p+10240, p+12544, 72, bcol, 16, lane);
        __syncthreads();
    }
    int r0 = arow + (lane >> 2), c0 = bcol + (lane & 3) * 2;
    size_t qb = (size_t)(h >> 1) * HS;
#pragma unroll
    for (int mi = 0; mi < 2; mi++)
#pragma unroll
        for (int ni = 0; ni < 4; ni++)
#pragma unroll
            for (int hf = 0; hf < 2; hf++) {
                int row = it*128 + r0 + mi*16 + hf*8;
                int col = jt*64 + c0 + ni*8;
                float2 q = *(const float2*)&g_QK[qb + (size_t)row*TT + col];
                *(float2*)&g_rhs[hb + (size_t)row*TT + col] = make_float2(
                    (q.x - acc[mi][ni][hf*2])   * ATT_SCALE,
                    (q.y - acc[mi][ni][hf*2+1]) * ATT_SCALE);
            }
}

__global__ __launch_bounds__(128)
void softmax_rows() {
    int i = blockIdx.x, h = blockIdx.y, tid = threadIdx.x;
    float* row = g_rhs + (size_t)h * HS + (size_t)i * TT;
    bf16* ph = g_Ph + (size_t)h * HS + (size_t)i * TT;
    bf16* pl = g_Pl + (size_t)h * HS + (size_t)i * TT;
    int n = i + 1;
    __shared__ float sh[4];
    float mx = -1e30f;
    for (int j = tid; j < n; j += 128) mx = fmaxf(mx, row[j]);
#pragma unroll
    for (int o = 16; o; o >>= 1) mx = fmaxf(mx, __shfl_xor_sync(~0u, mx, o));
    if ((tid & 31) == 0) sh[tid >> 5] = mx;
    __syncthreads();
    mx = fmaxf(fmaxf(sh[0], sh[1]), fmaxf(sh[2], sh[3]));
    __syncthreads();
    float sum = 0.f;
    for (int j = tid; j < n; j += 128) { float e = __expf(row[j] - mx); row[j] = e; sum += e; }
#pragma unroll
    for (int o = 16; o; o >>= 1) sum += __shfl_xor_sync(~0u, sum, o);
    if ((tid & 31) == 0) sh[tid >> 5] = sum;
    __syncthreads();
    sum = sh[0] + sh[1] + sh[2] + sh[3];
    float inv = 1.f / sum;
    for (int j = tid; j < TT; j += 128) {
        float p = (j < n) ? row[j] * inv : 0.f;
        bf16 hh = __float2bfloat16(p);
        ph[j] = hh;
        pl[j] = __float2bfloat16(p - __bfloat162float(hh));
    }
}

// ---- O2 = P @ V per head, pipelined ----
__global__ __launch_bounds__(256)
void tc_pv() {
    int it = blockIdx.x, h = blockIdx.y;
    extern __shared__ __align__(16) bf16 sm[];
    const int BUF = 14848;
    int tid = threadIdx.x, lane = tid & 31, w = tid >> 5;
    int arow = (w >> 1) * 32, bcol = (w & 1) * 32;
    size_t hb = (size_t)h * HS;
    const bf16* vh = g_vh + (size_t)(h >> 1) * 64;
    const bf16* vl = g_vl + (size_t)(h >> 1) * 64;
    float acc[2][4][4] = {};
    int nch = 2 * (2*it + 2);
    auto stg = [&](int b, int m) {
        int k0 = m * 32;
        bf16* p = sm + b * BUF;
        stage2a(p, p+5120, 40,
                g_Ph + hb + (size_t)(it*128)*TT + k0,
                g_Pl + hb + (size_t)(it*128)*TT + k0, TT, 128, 4, tid);
        stage2a(p+10240, p+12544, 72,
                vh + (size_t)k0 * 1024, vl + (size_t)k0 * 1024, 1024, 32, 8, tid);
        CPC();
    };
    stg(0, 0);
    for (int m = 0; m < nch; m++) {
        if (m+1 < nch) { stg((m+1)&1, m+1); CPW(1); } else CPW(0);
        __syncthreads();
        bf16* p = sm + (m&1)*BUF;
        mma_tile<true>(acc, p, p+5120, 40, arow, 0,  p+10240, p+12544, 72, bcol, 0,  lane);
        mma_tile<true>(acc, p, p+5120, 40, arow, 16, p+10240, p+12544, 72, bcol, 16, lane);
        __syncthreads();
    }
    int r0 = arow + (lane >> 2), c0 = bcol + (lane & 3) * 2;
#pragma unroll
    for (int mi = 0; mi < 2; mi++)
#pragma unroll
        for (int ni = 0; ni < 4; ni++)
#pragma unroll
            for (int hf = 0; hf < 2; hf++) {
                int row = it*128 + r0 + mi*16 + hf*8;
                int col = c0 + ni*8;
                st_split2(g_O2h, g_O2l, (size_t)row * 2048 + h*64 + col,
                          acc[mi][ni][hf*2], acc[mi][ni][hf*2+1]);
            }
}

// ---- small fp32 GEMM (wraw only) ----
__global__ __launch_bounds__(256)
void gemm_abt(const float* __restrict__ A, const float* __restrict__ B,
              float* __restrict__ C, int M, int N, int K,
              int lda, int ldb, int ldc) {
    __shared__ float As[16][64], Bs[16][64];
    int n0 = blockIdx.x * 64, m0 = blockIdx.y * 64;
    int tid = threadIdx.x;
    int r  = tid >> 2;
    int kq = (tid & 3) * 4;
    int tr4 = (tid >> 4) * 4, tc4 = (tid & 15) * 4;
    float acc[4][4] = {};
    for (int k0 = 0; k0 < K; k0 += 16) {
        float4 a4 = *(const float4*)(A + (size_t)(m0 + r) * lda + k0 + kq);
        As[kq+0][r]=a4.x; As[kq+1][r]=a4.y; As[kq+2][r]=a4.z; As[kq+3][r]=a4.w;
        if (n0 + r < N) {
            float4 b4 = *(const float4*)(B + (size_t)(n0 + r) * ldb + k0 + kq);
            Bs[kq+0][r]=b4.x; Bs[kq+1][r]=b4.y; Bs[kq+2][r]=b4.z; Bs[kq+3][r]=b4.w;
        } else {
            Bs[kq+0][r]=0.f; Bs[kq+1][r]=0.f; Bs[kq+2][r]=0.f; Bs[kq+3][r]=0.f;
        }
        __syncthreads();
#pragma unroll
        for (int kk = 0; kk < 16; kk++) {
            float4 a = *(const float4*)&As[kk][tr4];
            float4 b = *(const float4*)&Bs[kk][tc4];
            float av[4]={a.x,a.y,a.z,a.w}, bv[4]={b.x,b.y,b.z,b.w};
#pragma unroll
            for (int i=0;i<4;i++)
#pragma unroll
                for (int j=0;j<4;j++) acc[i][j] += av[i]*bv[j];
        }
        __syncthreads();
    }
#pragma unroll
    for (int i = 0; i < 4; i++)
#pragma unroll
        for (int j = 0; j < 4; j++) {
            int col = n0 + tc4 + j;
            if (col < N) C[(size_t)(m0 + tr4 + i) * ldc + col] = acc[i][j];
        }
}

__global__ void beta_fix(const float* __restrict__ tmp, const float* __restrict__ bias,
                         float* __restrict__ betah) {
    int idx = blockIdx.x * blockDim.x + threadIdx.x;
    int t = idx >> 5, hr = idx & 31;
    betah[hr*TT + t] = 2.f / (1.f + __expf(-(tmp[t*32 + hr] + bias[hr])));
}

__global__ __launch_bounds__(64)
void wdir_kernel(const float* __restrict__ wraw, const float* __restrict__ conv_w,
                 const float* __restrict__ omega, const float* __restrict__ phi) {
    int t = blockIdx.x, hr = blockIdx.y, d = threadIdx.x;
    int hkv = hr >> 1, r = hr & 1;
    int cA = hkv * 256 + (2*r) * 64 + d;
    int cB = cA + 64;
    float a = 0.f, b = 0.f;
#pragma unroll
    for (int i = 0; i < 3; i++) {
        int tt = t + i - 2;
        if (tt >= 0) {
            a += wraw[(size_t)tt * 4096 + cA] * conv_w[cA*3 + i];
            b += wraw[(size_t)tt * 4096 + cB] * conv_w[cB*3 + i];
        }
    }
    a = a / (1.f + expf(-a));
    b = b / (1.f + expf(-b));
    float th = omega[r] * (float)t + phi[r];
    float w = a * cosf(th) + b * sinf(th);
    float ss = w * w;
#pragma unroll
    for (int o = 16; o; o >>= 1) ss += __shfl_xor_sync(~0u, ss, o);
    __shared__ float sh[2];
    if ((d & 31) == 0) sh[d >> 5] = ss;
    __syncthreads();
    float tot = sh[0] + sh[1];
    float val = w * rsqrtf(tot + 1e-6f);
    size_t off = ((size_t)hr * TT + t) * 64 + d;
    bf16 hh = __float2bfloat16(val);
    g_wdh[off] = hh;
    g_wdl[off] = __float2bfloat16(val - __bfloat162float(hh));
}

#define GS(p, s) cudaGetSymbolAddress((void**)&p, s)

extern "C" void kernel_launch(void* const* d_in, const int* in_sizes, int n_in,
                              void* d_out, int out_size) {
    const float* x    = (const float*)d_in[0];
    const float* q_w  = (const float*)d_in[1];
    const float* k_w  = (const float*)d_in[2];
    const float* v_w  = (const float*)d_in[3];
    const float* w1   = (const float*)d_in[4];
    const float* w2   = (const float*)d_in[5];
    const float* cw   = (const float*)d_in[6];
    const float* btw  = (const float*)d_in[7];
    const float* btb  = (const float*)d_in[8];
    const float* ow   = (const float*)d_in[9];
    const float* omega= (const float*)d_in[10];
    const float* phi  = (const float*)d_in[11];
    float* out = (float*)d_out;

    float *pwlow,*pwraw,*pbtmp,*pbetah,*pQK;
    bf16 *pxh,*pxl,*pqwh,*pqwl,*pkwh,*pkwl,*pvwh,*pvwl,*powh,*powl;
    bf16 *pqh,*pql,*pkh,*pkl,*pvh,*pvl,*pwdh,*pwdl;
    bf16 *pMwh,*pMwl,*pQWh,*pQWl,*pO2h,*pO2l;
    float* prhs;
    GS(pwlow,g_wlow); GS(pwraw,g_wraw); GS(pbtmp,g_btmp); GS(pbetah,g_betah);
    GS(pQK,g_QK); GS(prhs,g_rhs);
    GS(pxh,g_xh); GS(pxl,g_xl); GS(pqwh,g_qwh); GS(pqwl,g_qwl);
    GS(pkwh,g_kwh); GS(pkwl,g_kwl); GS(pvwh,g_vwh); GS(pvwl,g_vwl);
    GS(powh,g_owh); GS(powl,g_owl);
    GS(pqh,g_qh); GS(pql,g_ql); GS(pkh,g_kh); GS(pkl,g_kl);
    GS(pvh,g_vh); GS(pvl,g_vl); GS(pwdh,g_wdh); GS(pwdl,g_wdl);
    GS(pMwh,g_Mwh); GS(pMwl,g_Mwl); GS(pQWh,g_QWh); GS(pQWl,g_QWl);
    GS(pO2h,g_O2h); GS(pO2l,g_O2l);

    static bool attr_done = false;
    if (!attr_done) {
        cudaFuncSetAttribute(tc_dense,  cudaFuncAttributeMaxDynamicSharedMemorySize, 61440);
        cudaFuncSetAttribute(tc_head,   cudaFuncAttributeMaxDynamicSharedMemorySize, 61440);
        cudaFuncSetAttribute(tc_solve,  cudaFuncAttributeMaxDynamicSharedMemorySize, 55296);
        cudaFuncSetAttribute(tc_logits, cudaFuncAttributeMaxDynamicSharedMemorySize, 59392);
        cudaFuncSetAttribute(tc_pv,     cudaFuncAttributeMaxDynamicSharedMemorySize, 59392);
        attr_done = true;
    }

    split_kernel<<<4096, 256>>>(x,   pxh,  pxl,  1048576);
    split_kernel<<<4096, 256>>>(q_w, pqwh, pqwl, 1048576);
    split_kernel<<<4096, 256>>>(k_w, pkwh, pkwl, 1048576);
    split_kernel<<<4096, 256>>>(v_w, pvwh, pvwl, 1048576);
    split_kernel<<<8192, 256>>>(ow,  powh, powl, 2097152);

    lowrank<<<1024, 256>>>(x, w1, btw, pwlow, pbtmp);
    gemm_abt<<<dim3(64,16), 256>>>(pwlow, w2, pwraw, 1024, 4096, 32, 32, 32, 4096);
    beta_fix<<<128, 256>>>(pbtmp, btb, pbetah);
    wdir_kernel<<<dim3(1024, 32), 64>>>(pwraw, cw, omega, phi);

    tc_dense<<<dim3(16,8), 256, 61440>>>(pxh, pxl, 1024, pqwh, pqwl, 1024, 1024, pqh, pql, nullptr, 1024);
    tc_dense<<<dim3(16,8), 256, 61440>>>(pxh, pxl, 1024, pkwh, pkwl, 1024, 1024, pkh, pkl, nullptr, 1024);
    tc_dense<<<dim3(16,8), 256, 61440>>>(pxh, pxl, 1024, pvwh, pvwl, 1024, 1024, pvh, pvl, nullptr, 1024);

    tc_head<<<dim3(16,8,32), 256, 61440>>>(pwdh, pwdl, 0, 65536, 64, pwdh, pwdl, 0, 65536, 64,
                                           pbetah, 1, pMwh, pMwl, nullptr);
    tc_head<<<dim3(16,8,32), 256, 61440>>>(pwdh, pwdl, 0, 65536, 64, pkh, pkl, 1, 64, 1024,
                                           pbetah, 1, nullptr, nullptr, prhs);
    // QK dedup: grid z=16, h IS the KV-head index -> hdiv must be 0 (offset h*64)
    tc_head<<<dim3(16,8,16), 256, 61440>>>(pqh, pql, 0, 64, 1024, pkh, pkl, 0, 64, 1024,
                                           nullptr, 2, nullptr, nullptr, pQK);
    tc_head<<<dim3(16,8,32), 256, 61440>>>(pqh, pql, 1, 64, 1024, pwdh, pwdl, 0, 65536, 64,
                                           nullptr, 2, pQWh, pQWl, nullptr);

    compute_tinv<<<dim3(16,32), 64>>>();
    for (int ci = 0; ci < 16; ci++)
        tc_solve<<<dim3(ci/2 + 1, 32), 256, 55296>>>(ci);

    tc_logits<<<dim3(16,8,32), 256, 59392>>>();
    softmax_rows<<<dim3(1024,32), 128>>>();
    tc_pv<<<dim3(8,32), 256, 59392>>>();

    tc_dense<<<dim3(16,8), 256, 61440>>>(pO2h, pO2l, 2048, powh, powl, 2048, 2048,
                                         nullptr, nullptr, out, 1024);
}

// round 9
// speedup vs baseline: 2.0345x; 1.0137x over previous
#include <cuda_runtime.h>
#include <cuda_bf16.h>
#include <cstdint>

using bf16 = __nv_bfloat16;
#define TT 1024
#define HS 1048576
#define ATT_SCALE 0.125f

__device__ float g_wlow[TT*32];
__device__ float g_wraw[TT*4096];
__device__ float g_btmp[TT*32];
__device__ float g_betah[32*TT];
__device__ float g_rhs[32*HS];
__device__ float g_QK [16*HS];

__device__ bf16 g_xh[1048576],  g_xl[1048576];
__device__ bf16 g_qwh[1048576], g_qwl[1048576];
__device__ bf16 g_kwh[1048576], g_kwl[1048576];
__device__ bf16 g_vwh[1048576], g_vwl[1048576];
__device__ bf16 g_owh[2097152], g_owl[2097152];
__device__ bf16 g_qh[1048576],  g_ql[1048576];
__device__ bf16 g_kh[1048576],  g_kl[1048576];
__device__ bf16 g_vh[1048576],  g_vl[1048576];
__device__ bf16 g_wdh[2097152], g_wdl[2097152];
__device__ bf16 g_Mwh[33554432], g_Mwl[33554432];
__device__ bf16 g_Bh [33554432], g_Bl [33554432];
__device__ bf16 g_QWh[33554432], g_QWl[33554432];
__device__ bf16 g_Ph [33554432], g_Pl [33554432];
__device__ bf16 g_Tvh[2097152],  g_Tvl[2097152];
__device__ bf16 g_O2h[2097152],  g_O2l[2097152];

__device__ __forceinline__ uint32_t sptr(const void* p) {
    return (uint32_t)__cvta_generic_to_shared(p);
}
__device__ __forceinline__ void ldsm4(uint32_t* r, uint32_t a) {
    asm volatile("ldmatrix.sync.aligned.m8n8.x4.shared.b16 {%0,%1,%2,%3}, [%4];"
        : "=r"(r[0]), "=r"(r[1]), "=r"(r[2]), "=r"(r[3]) : "r"(a));
}
__device__ __forceinline__ void ldsm4t(uint32_t* r, uint32_t a) {
    asm volatile("ldmatrix.sync.aligned.m8n8.x4.trans.shared.b16 {%0,%1,%2,%3}, [%4];"
        : "=r"(r[0]), "=r"(r[1]), "=r"(r[2]), "=r"(r[3]) : "r"(a));
}
__device__ __forceinline__ void mma_bf(float* c, const uint32_t* a, const uint32_t* b) {
    asm volatile(
        "mma.sync.aligned.m16n8k16.row.col.f32.bf16.bf16.f32 "
        "{%0,%1,%2,%3},{%4,%5,%6,%7},{%8,%9},{%0,%1,%2,%3};"
        : "+f"(c[0]), "+f"(c[1]), "+f"(c[2]), "+f"(c[3])
        : "r"(a[0]), "r"(a[1]), "r"(a[2]), "r"(a[3]), "r"(b[0]), "r"(b[1]));
}
__device__ __forceinline__ void st_split2(bf16* hi, bf16* lo, size_t off, float v0, float v1) {
    bf16 h0 = __float2bfloat16(v0), h1 = __float2bfloat16(v1);
    *(__nv_bfloat162*)(hi + off) = __halves2bfloat162(h0, h1);
    *(__nv_bfloat162*)(lo + off) = __halves2bfloat162(
        __float2bfloat16(v0 - __bfloat162float(h0)),
        __float2bfloat16(v1 - __bfloat162float(h1)));
}
__device__ __forceinline__ void cpa16(void* s, const void* g) {
    asm volatile("cp.async.cg.shared.global [%0], [%1], 16;" :: "r"(sptr(s)), "l"(g) : "memory");
}
#define CPC() asm volatile("cp.async.commit_group;" ::: "memory")
#define CPW(n) asm volatile("cp.async.wait_group %0;" :: "n"(n) : "memory")

template<bool TRANSB>
__device__ __forceinline__ void mma_tile(float (&acc)[2][4][4],
    const bf16* sAh, const bf16* sAl, int SA, int arow, int ka0,
    const bf16* sBh, const bf16* sBl, int SB, int bcol, int kb0, int lane)
{
    uint32_t ah[2][4], al[2][4];
    {
        int r = arow + (lane & 15);
        int c = ka0 + ((lane >> 4) << 3);
        ldsm4(ah[0], sptr(sAh + r * SA + c));
        ldsm4(ah[1], sptr(sAh + (r + 16) * SA + c));
        ldsm4(al[0], sptr(sAl + r * SA + c));
        ldsm4(al[1], sptr(sAl + (r + 16) * SA + c));
    }
    uint32_t bh[4][2], bl[4][2];
    int m = lane >> 3, rr = lane & 7;
#pragma unroll
    for (int g = 0; g < 2; g++) {
        uint32_t t[4];
        if (!TRANSB) {
            int n  = bcol + g * 16 + ((m >> 1) << 3) + rr;
            int kk = kb0 + ((m & 1) << 3);
            ldsm4(t, sptr(sBh + n * SB + kk));
            bh[2*g][0]=t[0]; bh[2*g][1]=t[1]; bh[2*g+1][0]=t[2]; bh[2*g+1][1]=t[3];
            ldsm4(t, sptr(sBl + n * SB + kk));
            bl[2*g][0]=t[0]; bl[2*g][1]=t[1]; bl[2*g+1][0]=t[2]; bl[2*g+1][1]=t[3];
        } else {
            int kr = kb0 + ((m & 1) << 3) + rr;
            int nc = bcol + g * 16 + ((m >> 1) << 3);
            ldsm4t(t, sptr(sBh + kr * SB + nc));
            bh[2*g][0]=t[0]; bh[2*g][1]=t[1]; bh[2*g+1][0]=t[2]; bh[2*g+1][1]=t[3];
            ldsm4t(t, sptr(sBl + kr * SB + nc));
            bl[2*g][0]=t[0]; bl[2*g][1]=t[1]; bl[2*g+1][0]=t[2]; bl[2*g+1][1]=t[3];
        }
    }
#pragma unroll
    for (int mi = 0; mi < 2; mi++)
#pragma unroll
        for (int ni = 0; ni < 4; ni++) {
            mma_bf(acc[mi][ni], ah[mi], bh[ni]);
            mma_bf(acc[mi][ni], ah[mi], bl[ni]);
            mma_bf(acc[mi][ni], al[mi], bh[ni]);
        }
}

__device__ __forceinline__ void stage2a(bf16* dh, bf16* dl, int stride,
    const bf16* gh, const bf16* gl, int ld, int rows, int c8, int tid)
{
    for (int i = tid; i < rows * c8; i += 256) {
        int r = i / c8, c = (i - r * c8) * 8;
        cpa16(dh + r * stride + c, gh + (size_t)r * ld + c);
        cpa16(dl + r * stride + c, gl + (size_t)r * ld + c);
    }
}

__global__ __launch_bounds__(256)
void split_kernel(const float* __restrict__ in, bf16* __restrict__ hi,
                  bf16* __restrict__ lo, int n) {
    int i = blockIdx.x * 256 + threadIdx.x;
    if (i < n) {
        float v = in[i];
        bf16 h = __float2bfloat16(v);
        hi[i] = h;
        lo[i] = __float2bfloat16(v - __bfloat162float(h));
    }
}

// ---- fused x@w1^T (32) and x@btw^T (32) per token ----
__global__ __launch_bounds__(256)
void lowrank(const float* __restrict__ x, const float* __restrict__ w1,
             const float* __restrict__ btw, float* __restrict__ wlow, float* __restrict__ btmp) {
    __shared__ float sx[1024];
    __shared__ float red[64][5];
    int t = blockIdx.x, tid = threadIdx.x;
    *(float4*)&sx[tid*4] = *(const float4*)&x[(size_t)t*1024 + tid*4];
    __syncthreads();
    int c = tid & 63, s = tid >> 6;
    const float* w = (c < 32) ? (w1 + (size_t)c*1024) : (btw + (size_t)(c-32)*1024);
    float acc = 0.f;
    for (int k = s*256; k < s*256 + 256; k += 4) {
        float4 wv = *(const float4*)&w[k];
        acc += wv.x*sx[k] + wv.y*sx[k+1] + wv.z*sx[k+2] + wv.w*sx[k+3];
    }
    red[c][s] = acc;
    __syncthreads();
    if (tid < 64) {
        float v = red[tid][0] + red[tid][1] + red[tid][2] + red[tid][3];
        if (tid < 32) wlow[t*32 + tid] = v;
        else          btmp[t*32 + tid - 32] = v;
    }
}

// ---- dense C = A@B^T, tile 128x64, 2-buffer pipeline (out-projection) ----
__global__ __launch_bounds__(256)
void tc_dense(const bf16* __restrict__ Ah, const bf16* __restrict__ Al, int lda,
              const bf16* __restrict__ Bh, const bf16* __restrict__ Bl, int ldb,
              int K, float* __restrict__ Cf, int ldc)
{
    extern __shared__ __align__(16) bf16 sm[];
    const int BUF = 15360;
    int tid = threadIdx.x, lane = tid & 31, w = tid >> 5;
    int m0 = blockIdx.y * 128, n0 = blockIdx.x * 64;
    int arow = (w >> 1) * 32, bcol = (w & 1) * 32;
    float acc[2][4][4] = {};
    int nk = K / 32;
    auto stg = [&](int b, int k0) {
        bf16* p = sm + b * BUF;
        stage2a(p, p+5120, 40, Ah + (size_t)m0*lda + k0, Al + (size_t)m0*lda + k0, lda, 128, 4, tid);
        stage2a(p+10240, p+12800, 40, Bh + (size_t)n0*ldb + k0, Bl + (size_t)n0*ldb + k0, ldb, 64, 4, tid);
        CPC();
    };
    stg(0, 0);
    for (int i = 0; i < nk; i++) {
        if (i+1 < nk) { stg((i+1)&1, (i+1)*32); CPW(1); } else CPW(0);
        __syncthreads();
        bf16* p = sm + (i&1)*BUF;
        mma_tile<false>(acc, p, p+5120, 40, arow, 0,  p+10240, p+12800, 40, bcol, 0,  lane);
        mma_tile<false>(acc, p, p+5120, 40, arow, 16, p+10240, p+12800, 40, bcol, 16, lane);
        __syncthreads();
    }
    int r0 = arow + (lane >> 2), c0 = bcol + (lane & 3) * 2;
#pragma unroll
    for (int mi = 0; mi < 2; mi++)
#pragma unroll
        for (int ni = 0; ni < 4; ni++)
#pragma unroll
            for (int hf = 0; hf < 2; hf++) {
                int row = m0 + r0 + mi*16 + hf*8;
                int col = n0 + c0 + ni*8;
                *(float2*)&Cf[(size_t)row * ldc + col] =
                    make_float2(acc[mi][ni][hf*2], acc[mi][ni][hf*2+1]);
            }
}

// ---- fused q/k/v projections, tile 128x64, 2-buffer pipeline ----
__global__ __launch_bounds__(256)
void tc_qkv()
{
    extern __shared__ __align__(16) bf16 sm[];
    const int BUF = 15360;
    const bf16 *Bh, *Bl; bf16 *Ch, *Cl;
    if (blockIdx.z == 0)      { Bh = g_qwh; Bl = g_qwl; Ch = g_qh; Cl = g_ql; }
    else if (blockIdx.z == 1) { Bh = g_kwh; Bl = g_kwl; Ch = g_kh; Cl = g_kl; }
    else                      { Bh = g_vwh; Bl = g_vwl; Ch = g_vh; Cl = g_vl; }
    int tid = threadIdx.x, lane = tid & 31, w = tid >> 5;
    int m0 = blockIdx.y * 128, n0 = blockIdx.x * 64;
    int arow = (w >> 1) * 32, bcol = (w & 1) * 32;
    float acc[2][4][4] = {};
    auto stg = [&](int b, int k0) {
        bf16* p = sm + b * BUF;
        stage2a(p, p+5120, 40, g_xh + (size_t)m0*1024 + k0, g_xl + (size_t)m0*1024 + k0, 1024, 128, 4, tid);
        stage2a(p+10240, p+12800, 40, Bh + (size_t)n0*1024 + k0, Bl + (size_t)n0*1024 + k0, 1024, 64, 4, tid);
        CPC();
    };
    stg(0, 0);
    for (int i = 0; i < 32; i++) {
        if (i+1 < 32) { stg((i+1)&1, (i+1)*32); CPW(1); } else CPW(0);
        __syncthreads();
        bf16* p = sm + (i&1)*BUF;
        mma_tile<false>(acc, p, p+5120, 40, arow, 0,  p+10240, p+12800, 40, bcol, 0,  lane);
        mma_tile<false>(acc, p, p+5120, 40, arow, 16, p+10240, p+12800, 40, bcol, 16, lane);
        __syncthreads();
    }
    int r0 = arow + (lane >> 2), c0 = bcol + (lane & 3) * 2;
#pragma unroll
    for (int mi = 0; mi < 2; mi++)
#pragma unroll
        for (int ni = 0; ni < 4; ni++)
#pragma unroll
            for (int hf = 0; hf < 2; hf++) {
                int row = m0 + r0 + mi*16 + hf*8;
                int col = n0 + c0 + ni*8;
                st_split2(Ch, Cl, (size_t)row * 1024 + col,
                          acc[mi][ni][hf*2], acc[mi][ni][hf*2+1]);
            }
}

// ---- fused per-head GEMMs: z encodes stage (Mw / rhs / QK / QW), K=64 ----
__global__ __launch_bounds__(256)
void tc_headz()
{
    int jt = blockIdx.x, it = blockIdx.y, z = blockIdx.z;
    if (jt > 2 * it + 1) return;
    int stage, h;
    if (z < 32)      { stage = 0; h = z; }
    else if (z < 64) { stage = 1; h = z - 32; }
    else if (z < 80) { stage = 2; h = z - 64; }
    else             { stage = 3; h = z - 80; }

    const bf16 *Ahp, *Alp, *Bhp, *Blp;
    int lda, ldb, mode;
    const float* rowscale = nullptr;
    if (stage == 0) {
        Ahp = g_wdh + (size_t)h*65536; Alp = g_wdl + (size_t)h*65536; lda = 64;
        Bhp = g_wdh + (size_t)h*65536; Blp = g_wdl + (size_t)h*65536; ldb = 64;
        mode = 1; rowscale = g_betah;
    } else if (stage == 1) {
        Ahp = g_wdh + (size_t)h*65536; Alp = g_wdl + (size_t)h*65536; lda = 64;
        Bhp = g_kh + (size_t)(h>>1)*64; Blp = g_kl + (size_t)(h>>1)*64; ldb = 1024;
        mode = 1; rowscale = g_betah;
    } else if (stage == 2) {
        Ahp = g_qh + (size_t)h*64; Alp = g_ql + (size_t)h*64; lda = 1024;
        Bhp = g_kh + (size_t)h*64; Blp = g_kl + (size_t)h*64; ldb = 1024;
        mode = 2;
    } else {
        Ahp = g_qh + (size_t)(h>>1)*64; Alp = g_ql + (size_t)(h>>1)*64; lda = 1024;
        Bhp = g_wdh + (size_t)h*65536; Blp = g_wdl + (size_t)h*65536; ldb = 64;
        mode = 2;
    }
    Ahp += (size_t)(it*128) * lda; Alp += (size_t)(it*128) * lda;
    Bhp += (size_t)(jt*64)  * ldb; Blp += (size_t)(jt*64)  * ldb;

    extern __shared__ __align__(16) bf16 sm[];
    const int BUF = 15360;
    int tid = threadIdx.x, lane = tid & 31, w = tid >> 5;
    int arow = (w >> 1) * 32, bcol = (w & 1) * 32;
    float acc[2][4][4] = {};
    auto stg = [&](int b, int k0) {
        bf16* p = sm + b * BUF;
        stage2a(p, p+5120, 40, Ahp + k0, Alp + k0, lda, 128, 4, tid);
        stage2a(p+10240, p+12800, 40, Bhp + k0, Blp + k0, ldb, 64, 4, tid);
        CPC();
    };
    stg(0, 0);
#pragma unroll
    for (int i = 0; i < 2; i++) {
        if (i == 0) { stg(1, 32); CPW(1); } else CPW(0);
        __syncthreads();
        bf16* p = sm + i*BUF;
        mma_tile<false>(acc, p, p+5120, 40, arow, 0,  p+10240, p+12800, 40, bcol, 0,  lane);
        mma_tile<false>(acc, p, p+5120, 40, arow, 16, p+10240, p+12800, 40, bcol, 16, lane);
        __syncthreads();
    }
    int r0 = arow + (lane >> 2), c0 = bcol + (lane & 3) * 2;
    size_t hb = (size_t)h * HS;
#pragma unroll
    for (int mi = 0; mi < 2; mi++)
#pragma unroll
        for (int ni = 0; ni < 4; ni++)
#pragma unroll
            for (int hf = 0; hf < 2; hf++) {
                int row = it*128 + r0 + mi*16 + hf*8;
                int col = jt*64 + c0 + ni*8;
                float v0 = acc[mi][ni][hf*2], v1 = acc[mi][ni][hf*2+1];
                float sc = rowscale ? rowscale[h * TT + row] : 1.f;
                v0 *= sc; v1 *= sc;
                if (mode == 1) { if (col   >= row) v0 = 0.f;
                                 if (col+1 >= row) v1 = 0.f; }
                else           { if (col   >  row) v0 = 0.f;
                                 if (col+1 >  row) v1 = 0.f; }
                size_t off = hb + (size_t)row * TT + col;
                if (stage == 0)      st_split2(g_Mwh, g_Mwl, off, v0, v1);
                else if (stage == 1) *(float2*)&g_rhs[off] = make_float2(v0, v1);
                else if (stage == 2) *(float2*)&g_QK[off]  = make_float2(v0, v1);
                else                 st_split2(g_QWh, g_QWl, off, v0, v1);
            }
}

__global__ __launch_bounds__(64)
void compute_tinv() {
    __shared__ float L[64][65];
    __shared__ float X[64][65];
    int ch = blockIdx.x, h = blockIdx.y, c = threadIdx.x;
    size_t base = (size_t)h * HS + (size_t)(ch*64) * TT + ch*64;
    for (int r = 0; r < 64; r++) {
        L[r][c] = __bfloat162float(g_Mwh[base + (size_t)r*TT + c]) +
                  __bfloat162float(g_Mwl[base + (size_t)r*TT + c]);
        X[r][c] = (r == c) ? 1.f : 0.f;
    }
    __syncthreads();
    for (int r = 1; r < 64; r++) {
        if (c < r) {
            float acc = 0.f;
            for (int s = c; s < r; s++) acc += L[r][s] * X[s][c];
            X[r][c] = -acc;
        }
        __syncthreads();
    }
    size_t ob = ((size_t)(h*16 + ch)) * 4096;
    for (int r = 0; r < 64; r++) {
        float v = X[r][c];
        bf16 hh = __float2bfloat16(v);
        g_Tvh[ob + r*64 + c] = hh;
        g_Tvl[ob + r*64 + c] = __float2bfloat16(v - __bfloat162float(hh));
    }
}

// ---- blocked forward substitution, chunk ci; tile 64x128, 2-buffer pipeline ----
__global__ __launch_bounds__(256)
void tc_solve(int ci) {
    extern __shared__ __align__(16) bf16 sm[];
    const int BUF = 13824;
    int jb = blockIdx.x, h = blockIdx.y;
    int tid = threadIdx.x, lane = tid & 31, w = tid >> 5;
    int arow = (w >> 2) * 32, bcol = (w & 3) * 32;
    size_t hb = (size_t)h * HS;
    int r0 = arow + (lane >> 2), c0 = bcol + (lane & 3) * 2;
    float acc[2][4][4];
#pragma unroll
    for (int mi = 0; mi < 2; mi++)
#pragma unroll
        for (int ni = 0; ni < 4; ni++)
#pragma unroll
            for (int hf = 0; hf < 2; hf++) {
                float2 v = *(const float2*)&g_rhs[hb +
                    (size_t)(ci*64 + r0 + mi*16 + hf*8) * TT + jb*128 + c0 + ni*8];
                acc[mi][ni][hf*2]   = -v.x;
                acc[mi][ni][hf*2+1] = -v.y;
            }
    int nch = 2 * (ci - 2*jb);
    auto stg = [&](int b, int m) {
        int s = 2*jb + (m >> 1), kc = (m & 1) * 32;
        bf16* p = sm + b * BUF;
        stage2a(p, p+2560, 40,
                g_Mwh + hb + (size_t)(ci*64)*TT + s*64 + kc,
                g_Mwl + hb + (size_t)(ci*64)*TT + s*64 + kc, TT, 64, 4, tid);
        stage2a(p+5120, p+9472, 136,
                g_Bh + hb + (size_t)(s*64 + kc)*TT + jb*128,
                g_Bl + hb + (size_t)(s*64 + kc)*TT + jb*128, TT, 32, 16, tid);
        CPC();
    };
    if (nch > 0) stg(0, 0);
    for (int m = 0; m < nch; m++) {
        if (m+1 < nch) { stg((m+1)&1, m+1); CPW(1); } else CPW(0);
        __syncthreads();
        bf16* p = sm + (m&1)*BUF;
        mma_tile<true>(acc, p, p+2560, 40, arow, 0,  p+5120, p+9472, 136, bcol, 0,  lane);
        mma_tile<true>(acc, p, p+2560, 40, arow, 16, p+5120, p+9472, 136, bcol, 16, lane);
        __syncthreads();
    }
    // phase 2: P into smem split, then Tinv @ P
    bf16 *sPh = sm, *sPl = sm + 8704, *sTh = sm + 17408, *sTl = sm + 19968;
    __syncthreads();
#pragma unroll
    for (int mi = 0; mi < 2; mi++)
#pragma unroll
        for (int ni = 0; ni < 4; ni++)
#pragma unroll
            for (int hf = 0; hf < 2; hf++) {
                int r = r0 + mi*16 + hf*8, c = c0 + ni*8;
                st_split2(sPh, sPl, (size_t)r*136 + c,
                          -acc[mi][ni][hf*2], -acc[mi][ni][hf*2+1]);
            }
#pragma unroll
    for (int mi = 0; mi < 2; mi++)
#pragma unroll
        for (int ni = 0; ni < 4; ni++)
#pragma unroll
            for (int e = 0; e < 4; e++) acc[mi][ni][e] = 0.f;
    size_t tb = ((size_t)(h*16 + ci)) * 4096;
#pragma unroll
    for (int kc = 0; kc < 64; kc += 32) {
        stage2a(sTh, sTl, 40, g_Tvh + tb + kc, g_Tvl + tb + kc, 64, 64, 4, tid);
        CPC(); CPW(0);
        __syncthreads();
        mma_tile<true>(acc, sTh, sTl, 40, arow, 0,  sPh, sPl, 136, bcol, kc,      lane);
        mma_tile<true>(acc, sTh, sTl, 40, arow, 16, sPh, sPl, 136, bcol, kc + 16, lane);
        __syncthreads();
    }
#pragma unroll
    for (int mi = 0; mi < 2; mi++)
#pragma unroll
        for (int ni = 0; ni < 4; ni++)
#pragma unroll
            for (int hf = 0; hf < 2; hf++) {
                int row = ci*64 + r0 + mi*16 + hf*8;
                int col = jb*128 + c0 + ni*8;
                st_split2(g_Bh, g_Bl, hb + (size_t)row*TT + col,
                          acc[mi][ni][hf*2], acc[mi][ni][hf*2+1]);
            }
}

// ---- logits = (qk - QW@Bmat)*scale -> g_rhs, 2-buffer pipeline ----
__global__ __launch_bounds__(256)
void tc_logits() {
    int jt = blockIdx.x, it = blockIdx.y, h = blockIdx.z;
    if (jt > 2 * it + 1) return;
    extern __shared__ __align__(16) bf16 sm[];
    const int BUF = 14848;
    int tid = threadIdx.x, lane = tid & 31, w = tid >> 5;
    int arow = (w >> 1) * 32, bcol = (w & 1) * 32;
    size_t hb = (size_t)h * HS;
    float acc[2][4][4] = {};
    int nch = 2 * (2*it + 2 - jt);
    auto stg = [&](int b, int m) {
        int kb = jt + (m >> 1), kc = (m & 1) * 32;
        bf16* p = sm + b * BUF;
        stage2a(p, p+5120, 40,
                g_QWh + hb + (size_t)(it*128)*TT + kb*64 + kc,
                g_QWl + hb + (size_t)(it*128)*TT + kb*64 + kc, TT, 128, 4, tid);
        stage2a(p+10240, p+12544, 72,
                g_Bh + hb + (size_t)(kb*64 + kc)*TT + jt*64,
                g_Bl + hb + (size_t)(kb*64 + kc)*TT + jt*64, TT, 32, 8, tid);
        CPC();
    };
    stg(0, 0);
    for (int m = 0; m < nch; m++) {
        if (m+1 < nch) { stg((m+1)&1, m+1); CPW(1); } else CPW(0);
        __syncthreads();
        bf16* p = sm + (m&1)*BUF;
        mma_tile<true>(acc, p, p+5120, 40, arow, 0,  p+10240, p+12544, 72, bcol, 0,  lane);
        mma_tile<true>(acc, p, p+5120, 40, arow, 16, p+10240, p+12544, 72, bcol, 16, lane);
        __syncthreads();
    }
    int r0 = arow + (lane >> 2), c0 = bcol + (lane & 3) * 2;
    size_t qb = (size_t)(h >> 1) * HS;
#pragma unroll
    for (int mi = 0; mi < 2; mi++)
#pragma unroll
        for (int ni = 0; ni < 4; ni++)
#pragma unroll
            for (int hf = 0; hf < 2; hf++) {
                int row = it*128 + r0 + mi*16 + hf*8;
                int col = jt*64 + c0 + ni*8;
                float2 q = *(const float2*)&g_QK[qb + (size_t)row*TT + col];
                *(float2*)&g_rhs[hb + (size_t)row*TT + col] = make_float2(
                    (q.x - acc[mi][ni][hf*2])   * ATT_SCALE,
                    (q.y - acc[mi][ni][hf*2+1]) * ATT_SCALE);
            }
}

__global__ __launch_bounds__(128)
void softmax_rows() {
    int i = blockIdx.x, h = blockIdx.y, tid = threadIdx.x;
    float* row = g_rhs + (size_t)h * HS + (size_t)i * TT;
    bf16* ph = g_Ph + (size_t)h * HS + (size_t)i * TT;
    bf16* pl = g_Pl + (size_t)h * HS + (size_t)i * TT;
    int n = i + 1;
    __shared__ float sh[4];
    float mx = -1e30f;
    for (int j = tid; j < n; j += 128) mx = fmaxf(mx, row[j]);
#pragma unroll
    for (int o = 16; o; o >>= 1) mx = fmaxf(mx, __shfl_xor_sync(~0u, mx, o));
    if ((tid & 31) == 0) sh[tid >> 5] = mx;
    __syncthreads();
    mx = fmaxf(fmaxf(sh[0], sh[1]), fmaxf(sh[2], sh[3]));
    __syncthreads();
    float sum = 0.f;
    for (int j = tid; j < n; j += 128) { float e = __expf(row[j] - mx); row[j] = e; sum += e; }
#pragma unroll
    for (int o = 16; o; o >>= 1) sum += __shfl_xor_sync(~0u, sum, o);
    if ((tid & 31) == 0) sh[tid >> 5] = sum;
    __syncthreads();
    sum = sh[0] + sh[1] + sh[2] + sh[3];
    float inv = 1.f / sum;
    for (int j = tid; j < TT; j += 128) {
        float p = (j < n) ? row[j] * inv : 0.f;
        bf16 hh = __float2bfloat16(p);
        ph[j] = hh;
        pl[j] = __float2bfloat16(p - __bfloat162float(hh));
    }
}

// ---- O2 = P @ V per head, 2-buffer pipeline ----
__global__ __launch_bounds__(256)
void tc_pv() {
    int it = blockIdx.x, h = blockIdx.y;
    extern __shared__ __align__(16) bf16 sm[];
    const int BUF = 14848;
    int tid = threadIdx.x, lane = tid & 31, w = tid >> 5;
    int arow = (w >> 1) * 32, bcol = (w & 1) * 32;
    size_t hb = (size_t)h * HS;
    const bf16* vh = g_vh + (size_t)(h >> 1) * 64;
    const bf16* vl = g_vl + (size_t)(h >> 1) * 64;
    float acc[2][4][4] = {};
    int nch = 2 * (2*it + 2);
    auto stg = [&](int b, int m) {
        int k0 = m * 32;
        bf16* p = sm + b * BUF;
        stage2a(p, p+5120, 40,
                g_Ph + hb + (size_t)(it*128)*TT + k0,
                g_Pl + hb + (size_t)(it*128)*TT + k0, TT, 128, 4, tid);
        stage2a(p+10240, p+12544, 72,
                vh + (size_t)k0 * 1024, vl + (size_t)k0 * 1024, 1024, 32, 8, tid);
        CPC();
    };
    stg(0, 0);
    for (int m = 0; m < nch; m++) {
        if (m+1 < nch) { stg((m+1)&1, m+1); CPW(1); } else CPW(0);
        __syncthreads();
        bf16* p = sm + (m&1)*BUF;
        mma_tile<true>(acc, p, p+5120, 40, arow, 0,  p+10240, p+12544, 72, bcol, 0,  lane);
        mma_tile<true>(acc, p, p+5120, 40, arow, 16, p+10240, p+12544, 72, bcol, 16, lane);
        __syncthreads();
    }
    int r0 = arow + (lane >> 2), c0 = bcol + (lane & 3) * 2;
#pragma unroll
    for (int mi = 0; mi < 2; mi++)
#pragma unroll
        for (int ni = 0; ni < 4; ni++)
#pragma unroll
            for (int hf = 0; hf < 2; hf++) {
                int row = it*128 + r0 + mi*16 + hf*8;
                int col = c0 + ni*8;
                st_split2(g_O2h, g_O2l, (size_t)row * 2048 + h*64 + col,
                          acc[mi][ni][hf*2], acc[mi][ni][hf*2+1]);
            }
}

// ---- small fp32 GEMM (wraw only) ----
__global__ __launch_bounds__(256)
void gemm_abt(const float* __restrict__ A, const float* __restrict__ B,
              float* __restrict__ C, int M, int N, int K,
              int lda, int ldb, int ldc) {
    __shared__ float As[16][64], Bs[16][64];
    int n0 = blockIdx.x * 64, m0 = blockIdx.y * 64;
    int tid = threadIdx.x;
    int r  = tid >> 2;
    int kq = (tid & 3) * 4;
    int tr4 = (tid >> 4) * 4, tc4 = (tid & 15) * 4;
    float acc[4][4] = {};
    for (int k0 = 0; k0 < K; k0 += 16) {
        float4 a4 = *(const float4*)(A + (size_t)(m0 + r) * lda + k0 + kq);
        As[kq+0][r]=a4.x; As[kq+1][r]=a4.y; As[kq+2][r]=a4.z; As[kq+3][r]=a4.w;
        if (n0 + r < N) {
            float4 b4 = *(const float4*)(B + (size_t)(n0 + r) * ldb + k0 + kq);
            Bs[kq+0][r]=b4.x; Bs[kq+1][r]=b4.y; Bs[kq+2][r]=b4.z; Bs[kq+3][r]=b4.w;
        } else {
            Bs[kq+0][r]=0.f; Bs[kq+1][r]=0.f; Bs[kq+2][r]=0.f; Bs[kq+3][r]=0.f;
        }
        __syncthreads();
#pragma unroll
        for (int kk = 0; kk < 16; kk++) {
            float4 a = *(const float4*)&As[kk][tr4];
            float4 b = *(const float4*)&Bs[kk][tc4];
            float av[4]={a.x,a.y,a.z,a.w}, bv[4]={b.x,b.y,b.z,b.w};
#pragma unroll
            for (int i=0;i<4;i++)
#pragma unroll
                for (int j=0;j<4;j++) acc[i][j] += av[i]*bv[j];
        }
        __syncthreads();
    }
#pragma unroll
    for (int i = 0; i < 4; i++)
#pragma unroll
        for (int j = 0; j < 4; j++) {
            int col = n0 + tc4 + j;
            if (col < N) C[(size_t)(m0 + tr4 + i) * ldc + col] = acc[i][j];
        }
}

__global__ void beta_fix(const float* __restrict__ tmp, const float* __restrict__ bias,
                         float* __restrict__ betah) {
    int idx = blockIdx.x * blockDim.x + threadIdx.x;
    int t = idx >> 5, hr = idx & 31;
    betah[hr*TT + t] = 2.f / (1.f + __expf(-(tmp[t*32 + hr] + bias[hr])));
}

__global__ __launch_bounds__(64)
void wdir_kernel(const float* __restrict__ wraw, const float* __restrict__ conv_w,
                 const float* __restrict__ omega, const float* __restrict__ phi) {
    int t = blockIdx.x, hr = blockIdx.y, d = threadIdx.x;
    int hkv = hr >> 1, r = hr & 1;
    int cA = hkv * 256 + (2*r) * 64 + d;
    int cB = cA + 64;
    float a = 0.f, b = 0.f;
#pragma unroll
    for (int i = 0; i < 3; i++) {
        int tt = t + i - 2;
        if (tt >= 0) {
            a += wraw[(size_t)tt * 4096 + cA] * conv_w[cA*3 + i];
            b += wraw[(size_t)tt * 4096 + cB] * conv_w[cB*3 + i];
        }
    }
    a = a / (1.f + expf(-a));
    b = b / (1.f + expf(-b));
    float th = omega[r] * (float)t + phi[r];
    float w = a * cosf(th) + b * sinf(th);
    float ss = w * w;
#pragma unroll
    for (int o = 16; o; o >>= 1) ss += __shfl_xor_sync(~0u, ss, o);
    __shared__ float sh[2];
    if ((d & 31) == 0) sh[d >> 5] = ss;
    __syncthreads();
    float tot = sh[0] + sh[1];
    float val = w * rsqrtf(tot + 1e-6f);
    size_t off = ((size_t)hr * TT + t) * 64 + d;
    bf16 hh = __float2bfloat16(val);
    g_wdh[off] = hh;
    g_wdl[off] = __float2bfloat16(val - __bfloat162float(hh));
}

#define GS(p, s) cudaGetSymbolAddress((void**)&p, s)

extern "C" void kernel_launch(void* const* d_in, const int* in_sizes, int n_in,
                              void* d_out, int out_size) {
    const float* x    = (const float*)d_in[0];
    const float* q_w  = (const float*)d_in[1];
    const float* k_w  = (const float*)d_in[2];
    const float* v_w  = (const float*)d_in[3];
    const float* w1   = (const float*)d_in[4];
    const float* w2   = (const float*)d_in[5];
    const float* cw   = (const float*)d_in[6];
    const float* btw  = (const float*)d_in[7];
    const float* btb  = (const float*)d_in[8];
    const float* ow   = (const float*)d_in[9];
    const float* omega= (const float*)d_in[10];
    const float* phi  = (const float*)d_in[11];
    float* out = (float*)d_out;

    float *pwlow,*pwraw,*pbtmp,*pbetah;
    bf16 *pxh,*pxl,*pqwh,*pqwl,*pkwh,*pkwl,*pvwh,*pvwl,*powh,*powl;
    bf16 *pO2h,*pO2l;
    GS(pwlow,g_wlow); GS(pwraw,g_wraw); GS(pbtmp,g_btmp); GS(pbetah,g_betah);
    GS(pxh,g_xh); GS(pxl,g_xl); GS(pqwh,g_qwh); GS(pqwl,g_qwl);
    GS(pkwh,g_kwh); GS(pkwl,g_kwl); GS(pvwh,g_vwh); GS(pvwl,g_vwl);
    GS(powh,g_owh); GS(powl,g_owl);
    GS(pO2h,g_O2h); GS(pO2l,g_O2l);

    static bool attr_done = false;
    if (!attr_done) {
        cudaFuncSetAttribute(tc_dense,  cudaFuncAttributeMaxDynamicSharedMemorySize, 61440);
        cudaFuncSetAttribute(tc_qkv,    cudaFuncAttributeMaxDynamicSharedMemorySize, 61440);
        cudaFuncSetAttribute(tc_headz,  cudaFuncAttributeMaxDynamicSharedMemorySize, 61440);
        cudaFuncSetAttribute(tc_solve,  cudaFuncAttributeMaxDynamicSharedMemorySize, 55296);
        cudaFuncSetAttribute(tc_logits, cudaFuncAttributeMaxDynamicSharedMemorySize, 59392);
        cudaFuncSetAttribute(tc_pv,     cudaFuncAttributeMaxDynamicSharedMemorySize, 59392);
        attr_done = true;
    }

    split_kernel<<<4096, 256>>>(x,   pxh,  pxl,  1048576);
    split_kernel<<<4096, 256>>>(q_w, pqwh, pqwl, 1048576);
    split_kernel<<<4096, 256>>>(k_w, pkwh, pkwl, 1048576);
    split_kernel<<<4096, 256>>>(v_w, pvwh, pvwl, 1048576);
    split_kernel<<<8192, 256>>>(ow,  powh, powl, 2097152);

    lowrank<<<1024, 256>>>(x, w1, btw, pwlow, pbtmp);
    gemm_abt<<<dim3(64,16), 256>>>(pwlow, w2, pwraw, 1024, 4096, 32, 32, 32, 4096);
    beta_fix<<<128, 256>>>(pbtmp, btb, pbetah);
    wdir_kernel<<<dim3(1024, 32), 64>>>(pwraw, cw, omega, phi);

    // fused q/k/v projections (384 blocks)
    tc_qkv<<<dim3(16,8,3), 256, 61440>>>();

    // fused per-head GEMMs: Mw (z 0..31), rhs (32..63), QK deduped (64..79), QW (80..111)
    tc_headz<<<dim3(16,8,112), 256, 61440>>>();

    compute_tinv<<<dim3(16,32), 64>>>();
    for (int ci = 0; ci < 16; ci++)
        tc_solve<<<dim3(ci/2 + 1, 32), 256, 55296>>>(ci);

    tc_logits<<<dim3(16,8,32), 256, 59392>>>();
    softmax_rows<<<dim3(1024,32), 128>>>();
    tc_pv<<<dim3(8,32), 256, 59392>>>();

    tc_dense<<<dim3(16,8), 256, 61440>>>(pO2h, pO2l, 2048, powh, powl, 2048, 2048,
                                         out, 1024);
}